// round 10
// baseline (speedup 1.0000x reference)
#include <cuda_runtime.h>
#include <math.h>
#include <stdint.h>

#define D_NODE 100
#define D_EDGE 172
#define D_TIME 100
#define NKV    372
#define DOUT   100
#define EMAX   320000
#define DMAX   20000
#define MINN   1e-15f
#define MAXN   0.996f
#define SLOPE  0.2f

__device__ float    g_Qd[DMAX * DOUT];
__device__ float    g_dsthyp[DMAX * D_NODE];
__device__ float    g_V[(size_t)EMAX * DOUT];
__device__ float    g_scores[EMAX * 2];
__device__ float    g_ez[EMAX * 2];
__device__ unsigned g_smax[DMAX * 2];
__device__ float    g_ssum[DMAX * 2];
__device__ float    g_hagg[DMAX * DOUT];
__device__ float    g_hb[4 * DOUT];
__device__ float    g_hb2[4];
__device__ float    g_ztf[D_TIME];
__device__ float    g_ztf_e2;
__device__ float    g_Bfrag[4 * 24576];   // per-chunk B fragments (tf32-rounded)

__device__ __forceinline__ float wsum32(float v) {
#pragma unroll
    for (int m = 16; m; m >>= 1) v += __shfl_xor_sync(0xffffffffu, v, m);
    return v;
}
__device__ __forceinline__ float artanh_f(float x) {
    x = fminf(fmaxf(x, -1.0f + 1e-7f), 1.0f - 1e-7f);
    return 0.5f * (log1pf(x) - log1pf(-x));
}
__device__ __forceinline__ void enc_scale(float ss, float& s, float& en) {
    float n = sqrtf(ss), nn = fmaxf(n, MINN);
    float t = tanhf(nn);
    en = fminf(t, MAXN);
    s = en / nn;
}
__device__ __forceinline__ void hyp_ab(float mxn2, float xn, float dot_mh, float hb2,
                                       float& alpha, float& beta, float& nprev) {
    float mxn = fmaxf(sqrtf(mxn2), MINN);
    float t = tanhf(mxn / xn * artanh_f(xn));
    float nres = fminf(t, MAXN);
    float s1 = nres / mxn;
    float x2 = nres * nres;
    float xy = s1 * dot_mh;
    float a = 1.f + 2.f * xy + hb2;
    float bb = 1.f - x2;
    float den = fmaxf(1.f + 2.f * xy + x2 * hb2, MINN);
    float n2 = fmaxf(a * a * x2 + 2.f * a * bb * xy + bb * bb * hb2, 0.f);
    float nout = sqrtf(n2) / den;
    float ps = nout > MAXN ? MAXN / nout : 1.f;
    alpha = ps * a * s1 / den;
    beta = ps * bb / den;
    nprev = fminf(nout, MAXN);
}
__device__ __forceinline__ unsigned fenc(float f) {
    unsigned b = __float_as_uint(f);
    return (b & 0x80000000u) ? ~b : (b | 0x80000000u);
}
__device__ __forceinline__ float fdec(unsigned u) {
    return __uint_as_float((u & 0x80000000u) ? (u & 0x7fffffffu) : ~u);
}
__device__ __forceinline__ float lrelu(float x) { return x > 0.f ? x : SLOPE * x; }
__device__ __forceinline__ float tf32r(float x) {
    uint32_t u;
    asm("cvt.rna.tf32.f32 %0, %1;" : "=r"(u) : "f"(x));
    return __uint_as_float(u);
}
__device__ __forceinline__ void mma_tf32(float* d, const uint32_t* a, const uint32_t* b) {
    asm volatile(
        "mma.sync.aligned.m16n8k8.row.col.f32.tf32.tf32.f32 "
        "{%0,%1,%2,%3}, {%4,%5,%6,%7}, {%8,%9}, {%0,%1,%2,%3};"
        : "+f"(d[0]), "+f"(d[1]), "+f"(d[2]), "+f"(d[3])
        : "r"(a[0]), "r"(a[1]), "r"(a[2]), "r"(a[3]), "r"(b[0]), "r"(b[1]));
}

// ---------------- k0 / k_small / k_bfrag -------------------------------------
__global__ void k_zero(int D) {
    int tid = blockIdx.x * blockDim.x + threadIdx.x;
    int nt = gridDim.x * blockDim.x;
    for (int i = tid; i < D * DOUT; i += nt) g_hagg[i] = 0.f;
    for (int i = tid; i < 2 * D; i += nt) { g_ssum[i] = 0.f; g_smax[i] = 0u; }
}
__global__ void k_small(const float* __restrict__ bq, const float* __restrict__ bk,
                        const float* __restrict__ bv, const float* __restrict__ bo,
                        const float* __restrict__ tb) {
    int w = threadIdx.x >> 5, l = threadIdx.x & 31;
    if (w < 5) {
        const float* bp = (w == 0) ? bq : (w == 1) ? bk : (w == 2) ? bv : (w == 3) ? bo : tb;
        float v[4]; float ss = 0.f;
#pragma unroll
        for (int m = 0; m < 4; ++m) {
            int o = l + 32 * m;
            float x = (o < DOUT) ? bp[o] : 0.f;
            if (w == 4) x = cosf(x);
            v[m] = (o < DOUT) ? x : 0.f;
            ss += v[m] * v[m];
        }
        ss = wsum32(ss);
        float s, en; enc_scale(ss, s, en);
#pragma unroll
        for (int m = 0; m < 4; ++m) {
            int o = l + 32 * m;
            if (o < DOUT) { if (w < 4) g_hb[w * DOUT + o] = v[m] * s; else g_ztf[o] = v[m] * s; }
        }
        if (l == 0) { if (w < 4) g_hb2[w] = en * en; else g_ztf_e2 = en * en; }
    }
}
// B fragments: one-time conversion of Wk/Wv into per-chunk mma fragment layout
__global__ void k_bfrag(const float* __restrict__ Wk, const float* __restrict__ Wv) {
    int i = blockIdx.x * blockDim.x + threadIdx.x;
    if (i >= 4 * 24576) return;
    int c = i / 24576, j = i % 24576;
    int nm = j / 96, kfl = j % 96;
    int mm = nm >> 7, n = nm & 127;
    int kf = c * 96 + kfl;
    float v = 0.f;
    if (n < 100 && kf < NKV) v = (mm ? Wv : Wk)[n * NKV + kf];
    int ksl = kfl >> 3, kc8 = kfl & 7;
    int lane_t = ((n & 7) << 2) | (kc8 & 3);
    int ii = kc8 >> 2;
    g_Bfrag[c * 24576 + ((((mm << 4) | (n >> 3)) * 12 + ksl) * 32 + lane_t) * 2 + ii] = tf32r(v);
}

// ---------------- k1: per-dst encode + Q projection --------------------------
__global__ void __launch_bounds__(256) k1_dst(const float* __restrict__ dst_h,
                                              const float* __restrict__ Wq, int D) {
    extern __shared__ float sm[];
    float* Ws = sm;
    float* Xs = sm + 200 * 133;
    __shared__ float s_xn[32];
    int t = threadIdx.x, w = t >> 5, l = t & 31;
    int rbase = blockIdx.x * 32;
    float ztf_e2 = g_ztf_e2;
    for (int i = 0; i < 4; ++i) {
        int r = w * 4 + i, gr = rbase + r;
        float* xr = Xs + r * 200;
        if (gr < D) {
            const float* dr = dst_h + (size_t)gr * D_NODE;
            float v[4]; float ss = 0.f;
#pragma unroll
            for (int m = 0; m < 4; ++m) { int o = l + 32 * m; v[m] = (o < 100) ? dr[o] : 0.f; ss += v[m] * v[m]; }
            ss = wsum32(ss);
            float s, en; enc_scale(ss, s, en);
#pragma unroll
            for (int m = 0; m < 4; ++m) {
                int o = l + 32 * m;
                if (o < 100) {
                    float h = v[m] * s;
                    xr[o] = h; xr[100 + o] = g_ztf[o];
                    g_dsthyp[(size_t)gr * 100 + o] = h;
                }
            }
            if (l == 0) s_xn[r] = fmaxf(sqrtf(en * en + ztf_e2), MINN);
        } else {
            for (int o = l; o < 200; o += 32) xr[o] = 0.f;
            if (l == 0) s_xn[r] = MINN;
        }
    }
    for (int i = t; i < 28 * 200; i += 256) { int o = 100 + i / 200, k = i % 200; Ws[k * 133 + o] = 0.f; }
    for (int i = t; i < 100 * 200; i += 256) { int o = i / 200, k = i % 200; Ws[k * 133 + o] = Wq[i]; }
    __syncthreads();
    int oc = t & 127, g = t >> 7;
    float acc[16];
#pragma unroll
    for (int rr = 0; rr < 16; ++rr) acc[rr] = 0.f;
    for (int k = 0; k < 200; ++k) {
        float wv = Ws[k * 133 + oc];
#pragma unroll
        for (int rr = 0; rr < 16; ++rr) acc[rr] = fmaf(Xs[(g * 16 + rr) * 200 + k], wv, acc[rr]);
    }
    __syncthreads();
    float* Ms = Ws;
    if (oc < 100) {
#pragma unroll
        for (int rr = 0; rr < 16; ++rr) Ms[(g * 16 + rr) * 104 + oc] = acc[rr];
    }
    __syncthreads();
    float hb2 = g_hb2[0];
    for (int i = 0; i < 4; ++i) {
        int r = w * 4 + i, gr = rbase + r;
        if (gr >= D) continue;
        float mv[4], hv[4]; float pn = 0.f, pd = 0.f;
#pragma unroll
        for (int m = 0; m < 4; ++m) {
            int o = l + 32 * m;
            float a = (o < 100) ? Ms[r * 104 + o] : 0.f;
            float h = (o < 100) ? g_hb[o] : 0.f;
            mv[m] = a; hv[m] = h; pn += a * a; pd += a * h;
        }
        pn = wsum32(pn); pd = wsum32(pd);
        float alpha, beta, np;
        hyp_ab(pn, s_xn[r], pd, hb2, alpha, beta, np);
#pragma unroll
        for (int m = 0; m < 4; ++m) {
            int o = l + 32 * m;
            if (o < 100) g_Qd[(size_t)gr * 100 + o] = alpha * mv[m] + beta * hv[m];
        }
    }
}

// ---------------- k2: mma.sync tf32 edge kernel ------------------------------
#define TE 64
__device__ __forceinline__ void xs_store(float* Xs, int e, int f, float v) {
    int mt = e >> 4, r = e & 15, ks = f >> 3, c = f & 7;
    int lane_t = ((r & 7) << 2) | (c & 3);
    int ii = ((c >> 2) << 1) | (r >> 3);
    Xs[(((mt * 48 + ks) << 5) + lane_t) * 4 + ii] = tf32r(v);
}
// base offset for segment off0: stores go at base + 512*m (m-step = 32 features)
__device__ __forceinline__ int xs_base(int e, int l, int off0) {
    int mt = e >> 4, r = e & 15;
    int c = (off0 + l) & 7;
    int ks0 = (off0 + l) >> 3;
    int lane_t = ((r & 7) << 2) | (c & 3);
    int ii = ((c >> 2) << 1) | (r >> 3);
    return (mt * 48 + ks0) * 128 + lane_t * 4 + ii;
}
__global__ void __launch_bounds__(512) k2_edge(
    const float* __restrict__ neigh, const float* __restrict__ edgef,
    const float* __restrict__ dtp, const int* __restrict__ edst,
    const float* __restrict__ tw, const float* __restrict__ tb, int E) {
    extern __shared__ float sm[];
    float* Xs = sm;            // 24576 floats
    float* Bs = sm + 24576;    // 24576 floats
    __shared__ float s_xn[TE];
    __shared__ int   s_dst[TE];
    __shared__ float s_hbk[DOUT], s_hbv[DOUT];
    __shared__ float s_hb2k, s_hb2v;
    int t = threadIdx.x, w = t >> 5, l = t & 31;
    int base = blockIdx.x * TE;

    // Phase A: encode 4 edges per warp into A-fragment layout (affine offsets)
    for (int i = 0; i < 4; ++i) {
        int e = w * 4 + i, ge = base + e;
        if (ge < E) {
            float ss, s, e1, e2, e3;
            const float* nr = neigh + (size_t)ge * D_NODE;
            float v[4]; ss = 0.f;
#pragma unroll
            for (int m = 0; m < 4; ++m) { int o = l + 32 * m; v[m] = (o < 100) ? nr[o] : 0.f; ss += v[m] * v[m]; }
            ss = wsum32(ss); enc_scale(ss, s, e1);
            {
                int b0 = xs_base(e, l, 0);
#pragma unroll
                for (int m = 0; m < 4; ++m) if (l + 32 * m < 100) Xs[b0 + 512 * m] = tf32r(v[m] * s);
            }
            const float* er2 = edgef + (size_t)ge * D_EDGE;
            float u[6]; ss = 0.f;
#pragma unroll
            for (int m = 0; m < 6; ++m) { int o = l + 32 * m; u[m] = (o < 172) ? er2[o] : 0.f; ss += u[m] * u[m]; }
            ss = wsum32(ss); enc_scale(ss, s, e2);
            {
                int b1 = xs_base(e, l, 100);
#pragma unroll
                for (int m = 0; m < 6; ++m) if (l + 32 * m < 172) Xs[b1 + 512 * m] = tf32r(u[m] * s);
            }
            float dtv = dtp[ge];
            float cc[4]; ss = 0.f;
#pragma unroll
            for (int m = 0; m < 4; ++m) {
                int o = l + 32 * m;
                float c = (o < 100) ? __cosf(fmaf(dtv, tw[o], tb[o])) : 0.f;
                cc[m] = c; ss += c * c;
            }
            ss = wsum32(ss); enc_scale(ss, s, e3);
            {
                int b2 = xs_base(e, l, 272);
#pragma unroll
                for (int m = 0; m < 4; ++m) if (l + 32 * m < 100) Xs[b2 + 512 * m] = tf32r(cc[m] * s);
            }
            if (l < 12) xs_store(Xs, e, 372 + l, 0.f);
            if (l == 0) { s_xn[e] = fmaxf(sqrtf(e1 * e1 + e2 * e2 + e3 * e3), MINN); s_dst[e] = edst[ge]; }
        } else {
            for (int o = l; o < 384; o += 32) xs_store(Xs, e, o, 0.f);
            if (l == 0) { s_xn[e] = MINN; s_dst[e] = 0; }
        }
    }
    for (int o = t; o < DOUT; o += 512) { s_hbk[o] = g_hb[1 * DOUT + o]; s_hbv[o] = g_hb[2 * DOUT + o]; }
    if (t == 0) { s_hb2k = g_hb2[1]; s_hb2v = g_hb2[2]; }

    // GEMM: warp = (mat, mgroup of 2 mtiles, ngroup of 4 ntiles)
    int mat = w >> 3, mg = (w >> 2) & 1, ng = w & 3;
    float acc[2][4][4];
#pragma unroll
    for (int a = 0; a < 2; ++a)
#pragma unroll
        for (int b = 0; b < 4; ++b)
#pragma unroll
            for (int cxx = 0; cxx < 4; ++cxx) acc[a][b][cxx] = 0.f;

    for (int c = 0; c < 4; ++c) {
        __syncthreads();
        // linear copy of precomputed fragments (L2-resident, no index math)
        {
            const float4* src = (const float4*)(g_Bfrag + c * 24576);
            float4* dstB = (float4*)Bs;
#pragma unroll
            for (int i = 0; i < 12; ++i) dstB[t + i * 512] = src[t + i * 512];
        }
        __syncthreads();
#pragma unroll
        for (int ksl = 0; ksl < 12; ++ksl) {
            int ks = c * 12 + ksl;
            uint32_t a0[4], a1[4];
            *(float4*)a0 = *(const float4*)(Xs + (((2 * mg) * 48 + ks) * 32 + l) * 4);
            *(float4*)a1 = *(const float4*)(Xs + (((2 * mg + 1) * 48 + ks) * 32 + l) * 4);
#pragma unroll
            for (int nt4 = 0; nt4 < 4; ++nt4) {
                int nt = ng * 4 + nt4;
                uint32_t b[2];
                *(float2*)b = *(const float2*)(Bs + (((mat * 16 + nt) * 12 + ksl) * 32 + l) * 2);
                mma_tf32(acc[0][nt4], a0, b);
                mma_tf32(acc[1][nt4], a1, b);
            }
        }
    }
    __syncthreads();
    float* Kt = Xs;               // [64][104]
    float* Vt = Xs + TE * 104;    // [64][104]
#pragma unroll
    for (int mi = 0; mi < 2; ++mi) {
        int r0 = (2 * mg + mi) * 16 + (l >> 2);
        float* dst = mat ? Vt : Kt;
#pragma unroll
        for (int nt4 = 0; nt4 < 4; ++nt4) {
            int ncol = ng * 32 + nt4 * 8 + (l & 3) * 2;
            if (ncol < 100) {
                dst[r0 * 104 + ncol]           = acc[mi][nt4][0];
                dst[r0 * 104 + ncol + 1]       = acc[mi][nt4][1];
                dst[(r0 + 8) * 104 + ncol]     = acc[mi][nt4][2];
                dst[(r0 + 8) * 104 + ncol + 1] = acc[mi][nt4][3];
            }
        }
    }
    __syncthreads();

    // Epilogue: per-edge hyperbolic rescale of K and V rows (in smem)
    float hb2k = s_hb2k, hb2v = s_hb2v;
    for (int i = 0; i < 4; ++i) {
        int e = w * 4 + i;
        float pnk = 0.f, pdk = 0.f, pnv = 0.f, pdv = 0.f;
        for (int o = l; o < DOUT; o += 32) {
            float kv = Kt[e * 104 + o], vv = Vt[e * 104 + o];
            pnk += kv * kv; pdk += kv * s_hbk[o];
            pnv += vv * vv; pdv += vv * s_hbv[o];
        }
        pnk = wsum32(pnk); pdk = wsum32(pdk);
        pnv = wsum32(pnv); pdv = wsum32(pdv);
        float alK, beK, alV, beV, np;
        hyp_ab(pnk, s_xn[e], pdk, hb2k, alK, beK, np);
        hyp_ab(pnv, s_xn[e], pdv, hb2v, alV, beV, np);
        for (int o = l; o < DOUT; o += 32) {
            Kt[e * 104 + o] = alK * Kt[e * 104 + o] + beK * s_hbk[o];
            Vt[e * 104 + o] = alV * Vt[e * 104 + o] + beV * s_hbv[o];
        }
    }
    __syncthreads();

    // Scores: 16 warps x 4 edges
    for (int i = 0; i < 4; ++i) {
        int e = w * 4 + i, ge = base + e;
        if (ge >= E) continue;
        int dv = s_dst[e];
        const float* q = g_Qd + (size_t)dv * DOUT;
        float s0 = 0.f, s1v = 0.f;
        for (int o = l; o < DOUT; o += 32) {
            float p = q[o] * Kt[e * 104 + o];
            if (o < 50) s0 += p; else s1v += p;
        }
        s0 = wsum32(s0); s1v = wsum32(s1v);
        if (l == 0) {
            float r0 = lrelu(s0), r1 = lrelu(s1v);
            g_scores[2 * ge] = r0; g_scores[2 * ge + 1] = r1;
            atomicMax(&g_smax[2 * dv], fenc(r0));
            atomicMax(&g_smax[2 * dv + 1], fenc(r1));
        }
    }
    // Coalesced V writeout
    for (int i = t; i < TE * 25; i += 512) {
        int e = i / 25, c4 = i % 25;
        int ge = base + e;
        if (ge < E) {
            float4 v = *(const float4*)(Vt + e * 104 + c4 * 4);
            *(float4*)(g_V + (size_t)ge * DOUT + c4 * 4) = v;
        }
    }
}

// ---------------- k3: exp + segment sum --------------------------------------
__global__ void k3_exp(const int* __restrict__ edst, int E) {
    int e = blockIdx.x * blockDim.x + threadIdx.x;
    if (e >= E) return;
    int d = edst[e];
    float z0 = __expf(g_scores[2 * e] - fdec(g_smax[2 * d]));
    float z1 = __expf(g_scores[2 * e + 1] - fdec(g_smax[2 * d + 1]));
    g_ez[2 * e] = z0; g_ez[2 * e + 1] = z1;
    atomicAdd(&g_ssum[2 * d], z0);
    atomicAdd(&g_ssum[2 * d + 1], z1);
}

// ---------------- k4: weighted scatter aggregate -----------------------------
__global__ void k4_agg(const int* __restrict__ edst, int E) {
    int gw = (blockIdx.x * blockDim.x + threadIdx.x) >> 5;
    int l = threadIdx.x & 31;
    if (gw >= E) return;
    int d = edst[gw];
    float a0 = g_ez[2 * gw] / fmaxf(g_ssum[2 * d], MINN);
    float a1 = g_ez[2 * gw + 1] / fmaxf(g_ssum[2 * d + 1], MINN);
    if (l < 25) {
        const float4* vr = (const float4*)(g_V + (size_t)gw * DOUT);
        float4 v = vr[l];
        int c0 = 4 * l;
        float4 r;
        r.x = v.x * (c0 + 0 < 50 ? a0 : a1);
        r.y = v.y * (c0 + 1 < 50 ? a0 : a1);
        r.z = v.z * (c0 + 2 < 50 ? a0 : a1);
        r.w = v.w * (c0 + 3 < 50 ? a0 : a1);
        float* hp = g_hagg + (size_t)d * DOUT + c0;
        asm volatile("red.global.add.v4.f32 [%0], {%1, %2, %3, %4};"
                     :: "l"(hp), "f"(r.x), "f"(r.y), "f"(r.z), "f"(r.w) : "memory");
    }
}

// ---------------- k5: O projection + HypAct + logmap0 + LayerNorm ------------
__global__ void __launch_bounds__(256) k5_final(const float* __restrict__ Wo,
                                                const float* __restrict__ lng,
                                                const float* __restrict__ lnb,
                                                float* __restrict__ out, int D) {
    extern __shared__ float sm[];
    float* Ws = sm;
    float* Xs = sm + 200 * 133;
    __shared__ float s_xn[32];
    int t = threadIdx.x, w = t >> 5, l = t & 31;
    int rbase = blockIdx.x * 32;
    for (int i = 0; i < 4; ++i) {
        int r = w * 4 + i, gr = rbase + r;
        float* xr = Xs + r * 200;
        if (gr < D) {
            const float* ha = g_hagg + (size_t)gr * DOUT;
            const float* dh = g_dsthyp + (size_t)gr * D_NODE;
            float ss = 0.f;
#pragma unroll
            for (int m = 0; m < 4; ++m) {
                int o = l + 32 * m;
                float a = (o < 100) ? ha[o] : 0.f;
                float b = (o < 100) ? dh[o] : 0.f;
                if (o < 100) { xr[o] = a; xr[100 + o] = b; }
                ss += a * a + b * b;
            }
            ss = wsum32(ss);
            if (l == 0) s_xn[r] = fmaxf(sqrtf(ss), MINN);
        } else {
            for (int o = l; o < 200; o += 32) xr[o] = 0.f;
            if (l == 0) s_xn[r] = MINN;
        }
    }
    for (int i = t; i < 28 * 200; i += 256) { int o = 100 + i / 200, k = i % 200; Ws[k * 133 + o] = 0.f; }
    for (int i = t; i < 100 * 200; i += 256) { int o = i / 200, k = i % 200; Ws[k * 133 + o] = Wo[i]; }
    __syncthreads();
    int oc = t & 127, g = t >> 7;
    float acc[16];
#pragma unroll
    for (int rr = 0; rr < 16; ++rr) acc[rr] = 0.f;
    for (int k = 0; k < 200; ++k) {
        float wv = Ws[k * 133 + oc];
#pragma unroll
        for (int rr = 0; rr < 16; ++rr) acc[rr] = fmaf(Xs[(g * 16 + rr) * 200 + k], wv, acc[rr]);
    }
    __syncthreads();
    float* Ms = Ws;
    if (oc < 100) {
#pragma unroll
        for (int rr = 0; rr < 16; ++rr) Ms[(g * 16 + rr) * 104 + oc] = acc[rr];
    }
    __syncthreads();
    float hb2 = g_hb2[3];
    for (int i = 0; i < 4; ++i) {
        int r = w * 4 + i, gr = rbase + r;
        if (gr >= D) continue;
        float mv[4], hv[4]; float pn = 0.f, pd = 0.f;
#pragma unroll
        for (int m = 0; m < 4; ++m) {
            int o = l + 32 * m;
            float a = (o < 100) ? Ms[r * 104 + o] : 0.f;
            float h = (o < 100) ? g_hb[3 * DOUT + o] : 0.f;
            mv[m] = a; hv[m] = h; pn += a * a; pd += a * h;
        }
        pn = wsum32(pn); pd = wsum32(pd);
        float alpha, beta, nprev;
        hyp_ab(pn, s_xn[r], pd, hb2, alpha, beta, nprev);
        float lc = artanh_f(nprev) / fmaxf(nprev, MINN);
        float u2v[4]; float uss = 0.f;
#pragma unroll
        for (int m = 0; m < 4; ++m) {
            float u2 = lrelu(lc * (alpha * mv[m] + beta * hv[m]));
            u2v[m] = u2; uss += u2 * u2;
        }
        uss = wsum32(uss);
        float s2, en3; enc_scale(uss, s2, en3);
        float hsc = artanh_f(en3) / fmaxf(en3, MINN) * s2;
        float hvv[4]; float hs = 0.f, hs2 = 0.f;
#pragma unroll
        for (int m = 0; m < 4; ++m) {
            int o = l + 32 * m;
            float h = hsc * u2v[m];
            hvv[m] = h;
            if (o < 100) { hs += h; hs2 += h * h; }
        }
        hs = wsum32(hs); hs2 = wsum32(hs2);
        float mu = hs * 0.01f;
        float var = hs2 * 0.01f - mu * mu;
        float inv = rsqrtf(var + 1e-5f);
#pragma unroll
        for (int m = 0; m < 4; ++m) {
            int o = l + 32 * m;
            if (o < 100) out[(size_t)gr * 100 + o] = (hvv[m] - mu) * inv * lng[o] + lnb[o];
        }
    }
}

extern "C" void kernel_launch(void* const* d_in, const int* in_sizes, int n_in,
                              void* d_out, int out_size) {
    const float* dst_h = (const float*)d_in[0];
    const float* neigh = (const float*)d_in[1];
    const float* edgef = (const float*)d_in[2];
    const float* dtp   = (const float*)d_in[3];
    const int*   edst  = (const int*)d_in[4];
    const float* Wq = (const float*)d_in[5];
    const float* bq = (const float*)d_in[6];
    const float* Wk = (const float*)d_in[7];
    const float* bk = (const float*)d_in[8];
    const float* Wv = (const float*)d_in[9];
    const float* bv = (const float*)d_in[10];
    const float* Wo = (const float*)d_in[11];
    const float* bo = (const float*)d_in[12];
    const float* tw = (const float*)d_in[13];
    const float* tb = (const float*)d_in[14];
    const float* lng = (const float*)d_in[15];
    const float* lnb = (const float*)d_in[16];
    float* out = (float*)d_out;
    int D = in_sizes[0] / D_NODE;
    int E = in_sizes[3];

    size_t smem1 = (200 * 133 + 32 * 200) * sizeof(float);   // 132000
    size_t smem2 = 2 * 24576 * sizeof(float);                // 196608
    cudaFuncSetAttribute(k1_dst,   cudaFuncAttributeMaxDynamicSharedMemorySize, (int)smem1);
    cudaFuncSetAttribute(k5_final, cudaFuncAttributeMaxDynamicSharedMemorySize, (int)smem1);
    cudaFuncSetAttribute(k2_edge,  cudaFuncAttributeMaxDynamicSharedMemorySize, (int)smem2);

    k_zero<<<2048, 256>>>(D);
    k_small<<<1, 160>>>(bq, bk, bv, bo, tb);
    k_bfrag<<<(4 * 24576 + 255) / 256, 256>>>(Wk, Wv);
    k1_dst<<<(D + 31) / 32, 256, smem1>>>(dst_h, Wq, D);
    k2_edge<<<(E + TE - 1) / TE, 512, smem2>>>(neigh, edgef, dtp, edst, tw, tb, E);
    k3_exp<<<(E + 255) / 256, 256>>>(edst, E);
    k4_agg<<<(E + 7) / 8, 256>>>(edst, E);
    k5_final<<<(D + 31) / 32, 256, smem1>>>(Wo, lng, lnb, out, D);
}

// round 12
// speedup vs baseline: 1.0831x; 1.0831x over previous
#include <cuda_runtime.h>
#include <math.h>
#include <stdint.h>

#define D_NODE 100
#define D_EDGE 172
#define D_TIME 100
#define NKV    372
#define DOUT   100
#define EMAX   320000
#define DMAX   20000
#define MINN   1e-15f
#define MAXN   0.996f
#define SLOPE  0.2f

__device__ float    g_Qd[DMAX * DOUT];
__device__ float    g_dsthyp[DMAX * D_NODE];
__device__ float    g_V[(size_t)EMAX * DOUT];
__device__ float    g_scores[EMAX * 2];
__device__ float    g_ez[EMAX * 2];
__device__ unsigned g_smax[DMAX * 2];
__device__ float    g_ssum[DMAX * 2];
__device__ float    g_hagg[DMAX * DOUT];
__device__ float    g_hb[4 * DOUT];
__device__ float    g_hb2[4];
__device__ float    g_ztf[D_TIME];
__device__ float    g_ztf_e2;

__device__ __forceinline__ float wsum32(float v) {
#pragma unroll
    for (int m = 16; m; m >>= 1) v += __shfl_xor_sync(0xffffffffu, v, m);
    return v;
}
__device__ __forceinline__ float artanh_f(float x) {
    x = fminf(fmaxf(x, -1.0f + 1e-7f), 1.0f - 1e-7f);
    return 0.5f * (log1pf(x) - log1pf(-x));
}
__device__ __forceinline__ void enc_scale(float ss, float& s, float& en) {
    float n = sqrtf(ss), nn = fmaxf(n, MINN);
    float t = tanhf(nn);
    en = fminf(t, MAXN);
    s = en / nn;
}
__device__ __forceinline__ void hyp_ab(float mxn2, float xn, float dot_mh, float hb2,
                                       float& alpha, float& beta, float& nprev) {
    float mxn = fmaxf(sqrtf(mxn2), MINN);
    float t = tanhf(mxn / xn * artanh_f(xn));
    float nres = fminf(t, MAXN);
    float s1 = nres / mxn;
    float x2 = nres * nres;
    float xy = s1 * dot_mh;
    float a = 1.f + 2.f * xy + hb2;
    float bb = 1.f - x2;
    float den = fmaxf(1.f + 2.f * xy + x2 * hb2, MINN);
    float n2 = fmaxf(a * a * x2 + 2.f * a * bb * xy + bb * bb * hb2, 0.f);
    float nout = sqrtf(n2) / den;
    float ps = nout > MAXN ? MAXN / nout : 1.f;
    alpha = ps * a * s1 / den;
    beta = ps * bb / den;
    nprev = fminf(nout, MAXN);
}
__device__ __forceinline__ unsigned fenc(float f) {
    unsigned b = __float_as_uint(f);
    return (b & 0x80000000u) ? ~b : (b | 0x80000000u);
}
__device__ __forceinline__ float fdec(unsigned u) {
    return __uint_as_float((u & 0x80000000u) ? (u & 0x7fffffffu) : ~u);
}
__device__ __forceinline__ float lrelu(float x) { return x > 0.f ? x : SLOPE * x; }
__device__ __forceinline__ float tf32r(float x) {
    uint32_t u;
    asm("cvt.rna.tf32.f32 %0, %1;" : "=r"(u) : "f"(x));
    return __uint_as_float(u);
}
__device__ __forceinline__ void mma_tf32(float* d, const uint32_t* a, const uint32_t* b) {
    asm volatile(
        "mma.sync.aligned.m16n8k8.row.col.f32.tf32.tf32.f32 "
        "{%0,%1,%2,%3}, {%4,%5,%6,%7}, {%8,%9}, {%0,%1,%2,%3};"
        : "+f"(d[0]), "+f"(d[1]), "+f"(d[2]), "+f"(d[3])
        : "r"(a[0]), "r"(a[1]), "r"(a[2]), "r"(a[3]), "r"(b[0]), "r"(b[1]));
}

// ---------------- k_small: hb vectors + ztf ----------------------------------
__global__ void k_small(const float* __restrict__ bq, const float* __restrict__ bk,
                        const float* __restrict__ bv, const float* __restrict__ bo,
                        const float* __restrict__ tb) {
    int w = threadIdx.x >> 5, l = threadIdx.x & 31;
    if (w < 5) {
        const float* bp = (w == 0) ? bq : (w == 1) ? bk : (w == 2) ? bv : (w == 3) ? bo : tb;
        float v[4]; float ss = 0.f;
#pragma unroll
        for (int m = 0; m < 4; ++m) {
            int o = l + 32 * m;
            float x = (o < DOUT) ? bp[o] : 0.f;
            if (w == 4) x = cosf(x);
            v[m] = (o < DOUT) ? x : 0.f;
            ss += v[m] * v[m];
        }
        ss = wsum32(ss);
        float s, en; enc_scale(ss, s, en);
#pragma unroll
        for (int m = 0; m < 4; ++m) {
            int o = l + 32 * m;
            if (o < DOUT) { if (w < 4) g_hb[w * DOUT + o] = v[m] * s; else g_ztf[o] = v[m] * s; }
        }
        if (l == 0) { if (w < 4) g_hb2[w] = en * en; else g_ztf_e2 = en * en; }
    }
}

// ---------------- k1: per-dst encode + Q projection (2 CTAs/SM) --------------
#define WSP 105
__global__ void __launch_bounds__(256) k1_dst(const float* __restrict__ dst_h,
                                              const float* __restrict__ Wq, int D) {
    extern __shared__ float sm[];
    float* Ws = sm;               // [200][105] -> reused as M [32][104]
    float* Xs = sm + 200 * WSP;   // [32][200]
    __shared__ float s_xn[32];
    int t = threadIdx.x, w = t >> 5, l = t & 31;
    int rbase = blockIdx.x * 32;
    float ztf_e2 = g_ztf_e2;
    for (int i = 0; i < 4; ++i) {
        int r = w * 4 + i, gr = rbase + r;
        float* xr = Xs + r * 200;
        if (gr < D) {
            const float* dr = dst_h + (size_t)gr * D_NODE;
            float v[4]; float ss = 0.f;
#pragma unroll
            for (int m = 0; m < 4; ++m) { int o = l + 32 * m; v[m] = (o < 100) ? dr[o] : 0.f; ss += v[m] * v[m]; }
            ss = wsum32(ss);
            float s, en; enc_scale(ss, s, en);
#pragma unroll
            for (int m = 0; m < 4; ++m) {
                int o = l + 32 * m;
                if (o < 100) {
                    float h = v[m] * s;
                    xr[o] = h; xr[100 + o] = g_ztf[o];
                    g_dsthyp[(size_t)gr * 100 + o] = h;
                }
            }
            if (l == 0) s_xn[r] = fmaxf(sqrtf(en * en + ztf_e2), MINN);
        } else {
            for (int o = l; o < 200; o += 32) xr[o] = 0.f;
            if (l == 0) s_xn[r] = MINN;
        }
    }
    for (int i = t; i < 5 * 200; i += 256) { int o = 100 + i / 200, k = i % 200; Ws[k * WSP + o] = 0.f; }
    for (int i = t; i < 100 * 200; i += 256) { int o = i / 200, k = i % 200; Ws[k * WSP + o] = Wq[i]; }
    __syncthreads();
    int oc = t & 127, g = t >> 7;
    int ocw = (oc < WSP) ? oc : 0;
    float acc[16];
#pragma unroll
    for (int rr = 0; rr < 16; ++rr) acc[rr] = 0.f;
    for (int k = 0; k < 200; ++k) {
        float wv = Ws[k * WSP + ocw];
#pragma unroll
        for (int rr = 0; rr < 16; ++rr) acc[rr] = fmaf(Xs[(g * 16 + rr) * 200 + k], wv, acc[rr]);
    }
    __syncthreads();
    float* Ms = Ws;
    if (oc < 100) {
#pragma unroll
        for (int rr = 0; rr < 16; ++rr) Ms[(g * 16 + rr) * 104 + oc] = acc[rr];
    }
    __syncthreads();
    float hb2 = g_hb2[0];
    for (int i = 0; i < 4; ++i) {
        int r = w * 4 + i, gr = rbase + r;
        if (gr >= D) continue;
        float mv[4], hv[4]; float pn = 0.f, pd = 0.f;
#pragma unroll
        for (int m = 0; m < 4; ++m) {
            int o = l + 32 * m;
            float a = (o < 100) ? Ms[r * 104 + o] : 0.f;
            float h = (o < 100) ? g_hb[o] : 0.f;
            mv[m] = a; hv[m] = h; pn += a * a; pd += a * h;
        }
        pn = wsum32(pn); pd = wsum32(pd);
        float alpha, beta, np;
        hyp_ab(pn, s_xn[r], pd, hb2, alpha, beta, np);
#pragma unroll
        for (int m = 0; m < 4; ++m) {
            int o = l + 32 * m;
            if (o < 100) g_Qd[(size_t)gr * 100 + o] = alpha * mv[m] + beta * hv[m];
        }
    }
}

// ---------------- k2: mma.sync tf32 edge kernel (R8-proven form) -------------
#define TE 64
__device__ __forceinline__ void xs_store(float* Xs, int e, int f, float v) {
    int mt = e >> 4, r = e & 15, ks = f >> 3, c = f & 7;
    int lane_t = ((r & 7) << 2) | (c & 3);
    int ii = ((c >> 2) << 1) | (r >> 3);
    Xs[(((mt * 48 + ks) << 5) + lane_t) * 4 + ii] = tf32r(v);
}
__global__ void __launch_bounds__(512) k2_edge(
    const float* __restrict__ neigh, const float* __restrict__ edgef,
    const float* __restrict__ dtp, const int* __restrict__ edst,
    const float* __restrict__ Wk, const float* __restrict__ Wv,
    const float* __restrict__ tw, const float* __restrict__ tb, int E) {
    extern __shared__ float sm[];
    float* Xs = sm;            // 24576 floats
    float* Bs = sm + 24576;    // 24576 floats
    __shared__ float s_xn[TE];
    __shared__ int   s_dst[TE];
    __shared__ float s_hbk[DOUT], s_hbv[DOUT];
    __shared__ float s_hb2k, s_hb2v;
    int t = threadIdx.x, w = t >> 5, l = t & 31;
    int base = blockIdx.x * TE;

    for (int i = 0; i < 4; ++i) {
        int e = w * 4 + i, ge = base + e;
        if (ge < E) {
            float ss, s, e1, e2, e3;
            const float* nr = neigh + (size_t)ge * D_NODE;
            float v[4]; ss = 0.f;
#pragma unroll
            for (int m = 0; m < 4; ++m) { int o = l + 32 * m; v[m] = (o < 100) ? nr[o] : 0.f; ss += v[m] * v[m]; }
            ss = wsum32(ss); enc_scale(ss, s, e1);
#pragma unroll
            for (int m = 0; m < 4; ++m) { int o = l + 32 * m; if (o < 100) xs_store(Xs, e, o, v[m] * s); }
            const float* er2 = edgef + (size_t)ge * D_EDGE;
            float u[6]; ss = 0.f;
#pragma unroll
            for (int m = 0; m < 6; ++m) { int o = l + 32 * m; u[m] = (o < 172) ? er2[o] : 0.f; ss += u[m] * u[m]; }
            ss = wsum32(ss); enc_scale(ss, s, e2);
#pragma unroll
            for (int m = 0; m < 6; ++m) { int o = l + 32 * m; if (o < 172) xs_store(Xs, e, 100 + o, u[m] * s); }
            float dtv = dtp[ge];
            float cc[4]; ss = 0.f;
#pragma unroll
            for (int m = 0; m < 4; ++m) {
                int o = l + 32 * m;
                float c = (o < 100) ? __cosf(fmaf(dtv, tw[o], tb[o])) : 0.f;
                cc[m] = c; ss += c * c;
            }
            ss = wsum32(ss); enc_scale(ss, s, e3);
#pragma unroll
            for (int m = 0; m < 4; ++m) { int o = l + 32 * m; if (o < 100) xs_store(Xs, e, 272 + o, cc[m] * s); }
            if (l < 12) xs_store(Xs, e, 372 + l, 0.f);
            if (l == 0) { s_xn[e] = fmaxf(sqrtf(e1 * e1 + e2 * e2 + e3 * e3), MINN); s_dst[e] = edst[ge]; }
        } else {
            for (int o = l; o < 384; o += 32) xs_store(Xs, e, o, 0.f);
            if (l == 0) { s_xn[e] = MINN; s_dst[e] = 0; }
        }
    }
    for (int o = t; o < DOUT; o += 512) { s_hbk[o] = g_hb[1 * DOUT + o]; s_hbv[o] = g_hb[2 * DOUT + o]; }
    if (t == 0) { s_hb2k = g_hb2[1]; s_hb2v = g_hb2[2]; }

    int mat = w >> 3, mg = (w >> 2) & 1, ng = w & 3;
    float acc[2][4][4];
#pragma unroll
    for (int a = 0; a < 2; ++a)
#pragma unroll
        for (int b = 0; b < 4; ++b)
#pragma unroll
            for (int cxx = 0; cxx < 4; ++cxx) acc[a][b][cxx] = 0.f;

    for (int c = 0; c < 4; ++c) {
        __syncthreads();
        for (int i = t; i < 24576; i += 512) {
            int nm = i / 96, kfl = i % 96;
            int mm = nm >> 7, n = nm & 127;
            int kf = c * 96 + kfl;
            float v = 0.f;
            if (n < 100 && kf < NKV) v = (mm ? Wv : Wk)[n * NKV + kf];
            int ksl = kfl >> 3, kc8 = kfl & 7;
            int lane_t = ((n & 7) << 2) | (kc8 & 3);
            int ii = kc8 >> 2;
            Bs[((((mm << 4) | (n >> 3)) * 12 + ksl) * 32 + lane_t) * 2 + ii] = tf32r(v);
        }
        __syncthreads();
#pragma unroll
        for (int ksl = 0; ksl < 12; ++ksl) {
            int ks = c * 12 + ksl;
            uint32_t a0[4], a1[4];
            *(float4*)a0 = *(const float4*)(Xs + (((2 * mg) * 48 + ks) * 32 + l) * 4);
            *(float4*)a1 = *(const float4*)(Xs + (((2 * mg + 1) * 48 + ks) * 32 + l) * 4);
#pragma unroll
            for (int nt4 = 0; nt4 < 4; ++nt4) {
                int nt = ng * 4 + nt4;
                uint32_t b[2];
                *(float2*)b = *(const float2*)(Bs + (((mat * 16 + nt) * 12 + ksl) * 32 + l) * 2);
                mma_tf32(acc[0][nt4], a0, b);
                mma_tf32(acc[1][nt4], a1, b);
            }
        }
    }
    __syncthreads();
    float* Kt = Xs;               // [64][104]
    float* Vt = Xs + TE * 104;    // [64][104]
#pragma unroll
    for (int mi = 0; mi < 2; ++mi) {
        int r0 = (2 * mg + mi) * 16 + (l >> 2);
        float* dst = mat ? Vt : Kt;
#pragma unroll
        for (int nt4 = 0; nt4 < 4; ++nt4) {
            int ncol = ng * 32 + nt4 * 8 + (l & 3) * 2;
            if (ncol < 100) {
                dst[r0 * 104 + ncol]           = acc[mi][nt4][0];
                dst[r0 * 104 + ncol + 1]       = acc[mi][nt4][1];
                dst[(r0 + 8) * 104 + ncol]     = acc[mi][nt4][2];
                dst[(r0 + 8) * 104 + ncol + 1] = acc[mi][nt4][3];
            }
        }
    }
    __syncthreads();

    float hb2k = s_hb2k, hb2v = s_hb2v;
    for (int i = 0; i < 4; ++i) {
        int e = w * 4 + i;
        float pnk = 0.f, pdk = 0.f, pnv = 0.f, pdv = 0.f;
        for (int o = l; o < DOUT; o += 32) {
            float kv = Kt[e * 104 + o], vv = Vt[e * 104 + o];
            pnk += kv * kv; pdk += kv * s_hbk[o];
            pnv += vv * vv; pdv += vv * s_hbv[o];
        }
        pnk = wsum32(pnk); pdk = wsum32(pdk);
        pnv = wsum32(pnv); pdv = wsum32(pdv);
        float alK, beK, alV, beV, np;
        hyp_ab(pnk, s_xn[e], pdk, hb2k, alK, beK, np);
        hyp_ab(pnv, s_xn[e], pdv, hb2v, alV, beV, np);
        for (int o = l; o < DOUT; o += 32) {
            Kt[e * 104 + o] = alK * Kt[e * 104 + o] + beK * s_hbk[o];
            Vt[e * 104 + o] = alV * Vt[e * 104 + o] + beV * s_hbv[o];
        }
    }
    __syncthreads();

    for (int i = 0; i < 4; ++i) {
        int e = w * 4 + i, ge = base + e;
        if (ge >= E) continue;
        int dv = s_dst[e];
        const float* q = g_Qd + (size_t)dv * DOUT;
        float s0 = 0.f, s1v = 0.f;
        for (int o = l; o < DOUT; o += 32) {
            float p = q[o] * Kt[e * 104 + o];
            if (o < 50) s0 += p; else s1v += p;
        }
        s0 = wsum32(s0); s1v = wsum32(s1v);
        if (l == 0) {
            float r0 = lrelu(s0), r1 = lrelu(s1v);
            g_scores[2 * ge] = r0; g_scores[2 * ge + 1] = r1;
            atomicMax(&g_smax[2 * dv], fenc(r0));
            atomicMax(&g_smax[2 * dv + 1], fenc(r1));
        }
    }
    for (int i = t; i < TE * 25; i += 512) {
        int e = i / 25, c4 = i % 25;
        int ge = base + e;
        if (ge < E) {
            float4 v = *(const float4*)(Vt + e * 104 + c4 * 4);
            *(float4*)(g_V + (size_t)ge * DOUT + c4 * 4) = v;
        }
    }
}

// ---------------- k3: exp + segment sum --------------------------------------
__global__ void k3_exp(const int* __restrict__ edst, int E) {
    int e = blockIdx.x * blockDim.x + threadIdx.x;
    if (e >= E) return;
    int d = edst[e];
    float z0 = __expf(g_scores[2 * e] - fdec(g_smax[2 * d]));
    float z1 = __expf(g_scores[2 * e + 1] - fdec(g_smax[2 * d + 1]));
    g_ez[2 * e] = z0; g_ez[2 * e + 1] = z1;
    atomicAdd(&g_ssum[2 * d], z0);
    atomicAdd(&g_ssum[2 * d + 1], z1);
}

// ---------------- k4: weighted scatter aggregate -----------------------------
__global__ void k4_agg(const int* __restrict__ edst, int E) {
    int gw = (blockIdx.x * blockDim.x + threadIdx.x) >> 5;
    int l = threadIdx.x & 31;
    if (gw >= E) return;
    int d = edst[gw];
    float a0 = g_ez[2 * gw] / fmaxf(g_ssum[2 * d], MINN);
    float a1 = g_ez[2 * gw + 1] / fmaxf(g_ssum[2 * d + 1], MINN);
    if (l < 25) {
        const float4* vr = (const float4*)(g_V + (size_t)gw * DOUT);
        float4 v = vr[l];
        int c0 = 4 * l;
        float4 r;
        r.x = v.x * (c0 + 0 < 50 ? a0 : a1);
        r.y = v.y * (c0 + 1 < 50 ? a0 : a1);
        r.z = v.z * (c0 + 2 < 50 ? a0 : a1);
        r.w = v.w * (c0 + 3 < 50 ? a0 : a1);
        float* hp = g_hagg + (size_t)d * DOUT + c0;
        asm volatile("red.global.add.v4.f32 [%0], {%1, %2, %3, %4};"
                     :: "l"(hp), "f"(r.x), "f"(r.y), "f"(r.z), "f"(r.w) : "memory");
    }
}

// ---------------- k5: O projection + HypAct + logmap0 + LayerNorm ------------
__global__ void __launch_bounds__(256) k5_final(const float* __restrict__ Wo,
                                                const float* __restrict__ lng,
                                                const float* __restrict__ lnb,
                                                float* __restrict__ out, int D) {
    extern __shared__ float sm[];
    float* Ws = sm;               // [200][105] -> reused as M [32][104]
    float* Xs = sm + 200 * WSP;
    __shared__ float s_xn[32];
    int t = threadIdx.x, w = t >> 5, l = t & 31;
    int rbase = blockIdx.x * 32;
    for (int i = 0; i < 4; ++i) {
        int r = w * 4 + i, gr = rbase + r;
        float* xr = Xs + r * 200;
        if (gr < D) {
            const float* ha = g_hagg + (size_t)gr * DOUT;
            const float* dh = g_dsthyp + (size_t)gr * D_NODE;
            float ss = 0.f;
#pragma unroll
            for (int m = 0; m < 4; ++m) {
                int o = l + 32 * m;
                float a = (o < 100) ? ha[o] : 0.f;
                float b = (o < 100) ? dh[o] : 0.f;
                if (o < 100) { xr[o] = a; xr[100 + o] = b; }
                ss += a * a + b * b;
            }
            ss = wsum32(ss);
            if (l == 0) s_xn[r] = fmaxf(sqrtf(ss), MINN);
        } else {
            for (int o = l; o < 200; o += 32) xr[o] = 0.f;
            if (l == 0) s_xn[r] = MINN;
        }
    }
    for (int i = t; i < 5 * 200; i += 256) { int o = 100 + i / 200, k = i % 200; Ws[k * WSP + o] = 0.f; }
    for (int i = t; i < 100 * 200; i += 256) { int o = i / 200, k = i % 200; Ws[k * WSP + o] = Wo[i]; }
    __syncthreads();
    int oc = t & 127, g = t >> 7;
    int ocw = (oc < WSP) ? oc : 0;
    float acc[16];
#pragma unroll
    for (int rr = 0; rr < 16; ++rr) acc[rr] = 0.f;
    for (int k = 0; k < 200; ++k) {
        float wv = Ws[k * WSP + ocw];
#pragma unroll
        for (int rr = 0; rr < 16; ++rr) acc[rr] = fmaf(Xs[(g * 16 + rr) * 200 + k], wv, acc[rr]);
    }
    __syncthreads();
    float* Ms = Ws;
    if (oc < 100) {
#pragma unroll
        for (int rr = 0; rr < 16; ++rr) Ms[(g * 16 + rr) * 104 + oc] = acc[rr];
    }
    __syncthreads();
    float hb2 = g_hb2[3];
    for (int i = 0; i < 4; ++i) {
        int r = w * 4 + i, gr = rbase + r;
        if (gr >= D) continue;
        float mv[4], hv[4]; float pn = 0.f, pd = 0.f;
#pragma unroll
        for (int m = 0; m < 4; ++m) {
            int o = l + 32 * m;
            float a = (o < 100) ? Ms[r * 104 + o] : 0.f;
            float h = (o < 100) ? g_hb[3 * DOUT + o] : 0.f;
            mv[m] = a; hv[m] = h; pn += a * a; pd += a * h;
        }
        pn = wsum32(pn); pd = wsum32(pd);
        float alpha, beta, nprev;
        hyp_ab(pn, s_xn[r], pd, hb2, alpha, beta, nprev);
        float lc = artanh_f(nprev) / fmaxf(nprev, MINN);
        float u2v[4]; float uss = 0.f;
#pragma unroll
        for (int m = 0; m < 4; ++m) {
            float u2 = lrelu(lc * (alpha * mv[m] + beta * hv[m]));
            u2v[m] = u2; uss += u2 * u2;
        }
        uss = wsum32(uss);
        float s2, en3; enc_scale(uss, s2, en3);
        float hsc = artanh_f(en3) / fmaxf(en3, MINN) * s2;
        float hvv[4]; float hs = 0.f, hs2 = 0.f;
#pragma unroll
        for (int m = 0; m < 4; ++m) {
            int o = l + 32 * m;
            float h = hsc * u2v[m];
            hvv[m] = h;
            if (o < 100) { hs += h; hs2 += h * h; }
        }
        hs = wsum32(hs); hs2 = wsum32(hs2);
        float mu = hs * 0.01f;
        float var = hs2 * 0.01f - mu * mu;
        float inv = rsqrtf(var + 1e-5f);
#pragma unroll
        for (int m = 0; m < 4; ++m) {
            int o = l + 32 * m;
            if (o < 100) out[(size_t)gr * 100 + o] = (hvv[m] - mu) * inv * lng[o] + lnb[o];
        }
    }
}

extern "C" void kernel_launch(void* const* d_in, const int* in_sizes, int n_in,
                              void* d_out, int out_size) {
    const float* dst_h = (const float*)d_in[0];
    const float* neigh = (const float*)d_in[1];
    const float* edgef = (const float*)d_in[2];
    const float* dtp   = (const float*)d_in[3];
    const int*   edst  = (const int*)d_in[4];
    const float* Wq = (const float*)d_in[5];
    const float* bq = (const float*)d_in[6];
    const float* Wk = (const float*)d_in[7];
    const float* bk = (const float*)d_in[8];
    const float* Wv = (const float*)d_in[9];
    const float* bv = (const float*)d_in[10];
    const float* Wo = (const float*)d_in[11];
    const float* bo = (const float*)d_in[12];
    const float* tw = (const float*)d_in[13];
    const float* tb = (const float*)d_in[14];
    const float* lng = (const float*)d_in[15];
    const float* lnb = (const float*)d_in[16];
    float* out = (float*)d_out;
    int D = in_sizes[0] / D_NODE;
    int E = in_sizes[3];

    // accumulator init via memset nodes (graph-capturable, no allocs)
    void *p_hagg = nullptr, *p_ssum = nullptr, *p_smax = nullptr;
    cudaGetSymbolAddress(&p_hagg, g_hagg);
    cudaGetSymbolAddress(&p_ssum, g_ssum);
    cudaGetSymbolAddress(&p_smax, g_smax);
    cudaMemsetAsync(p_hagg, 0, (size_t)D * DOUT * sizeof(float));
    cudaMemsetAsync(p_ssum, 0, (size_t)2 * D * sizeof(float));
    cudaMemsetAsync(p_smax, 0, (size_t)2 * D * sizeof(unsigned));

    size_t smem1 = (200 * WSP + 32 * 200) * sizeof(float);   // 109600
    size_t smem2 = 2 * 24576 * sizeof(float);                // 196608
    cudaFuncSetAttribute(k1_dst,   cudaFuncAttributeMaxDynamicSharedMemorySize, (int)smem1);
    cudaFuncSetAttribute(k5_final, cudaFuncAttributeMaxDynamicSharedMemorySize, (int)smem1);
    cudaFuncSetAttribute(k2_edge,  cudaFuncAttributeMaxDynamicSharedMemorySize, (int)smem2);

    k_small<<<1, 160>>>(bq, bk, bv, bo, tb);
    k1_dst<<<(D + 31) / 32, 256, smem1>>>(dst_h, Wq, D);
    k2_edge<<<(E + TE - 1) / TE, 512, smem2>>>(neigh, edgef, dtp, edst, Wk, Wv, tw, tb, E);
    k3_exp<<<(E + 255) / 256, 256>>>(edst, E);
    k4_agg<<<(E + 7) / 8, 256>>>(edst, E);
    k5_final<<<(D + 31) / 32, 256, smem1>>>(Wo, lng, lnb, out, D);
}

// round 13
// speedup vs baseline: 1.4478x; 1.3368x over previous
#include <cuda_runtime.h>
#include <math.h>
#include <stdint.h>

#define D_NODE 100
#define D_EDGE 172
#define D_TIME 100
#define NKV    372
#define DOUT   100
#define EMAX   320000
#define DMAX   20000
#define MINN   1e-15f
#define MAXN   0.996f
#define SLOPE  0.2f

__device__ float    g_Qd[DMAX * DOUT];
__device__ float    g_dsthyp[DMAX * D_NODE];
__device__ float    g_V[(size_t)EMAX * DOUT];
__device__ float    g_scores[EMAX * 2];
__device__ unsigned g_smax[DMAX * 2];
__device__ float    g_ssum[DMAX * 2];
__device__ float    g_hagg[DMAX * DOUT];
__device__ float    g_hb[4 * DOUT];
__device__ float    g_hb2[4];
__device__ float    g_ztf[D_TIME];
__device__ float    g_ztf_e2;
__device__ __align__(16) float g_Bfrag[8 * 12288];  // 8 half-chunks, fragment layout

__device__ __forceinline__ float wsum32(float v) {
#pragma unroll
    for (int m = 16; m; m >>= 1) v += __shfl_xor_sync(0xffffffffu, v, m);
    return v;
}
__device__ __forceinline__ float artanh_f(float x) {
    x = fminf(fmaxf(x, -1.0f + 1e-7f), 1.0f - 1e-7f);
    return 0.5f * (log1pf(x) - log1pf(-x));
}
__device__ __forceinline__ void enc_scale(float ss, float& s, float& en) {
    float n = sqrtf(ss), nn = fmaxf(n, MINN);
    float t = tanhf(nn);
    en = fminf(t, MAXN);
    s = en / nn;
}
__device__ __forceinline__ void hyp_ab(float mxn2, float xn, float dot_mh, float hb2,
                                       float& alpha, float& beta, float& nprev) {
    float mxn = fmaxf(sqrtf(mxn2), MINN);
    float t = tanhf(mxn / xn * artanh_f(xn));
    float nres = fminf(t, MAXN);
    float s1 = nres / mxn;
    float x2 = nres * nres;
    float xy = s1 * dot_mh;
    float a = 1.f + 2.f * xy + hb2;
    float bb = 1.f - x2;
    float den = fmaxf(1.f + 2.f * xy + x2 * hb2, MINN);
    float n2 = fmaxf(a * a * x2 + 2.f * a * bb * xy + bb * bb * hb2, 0.f);
    float nout = sqrtf(n2) / den;
    float ps = nout > MAXN ? MAXN / nout : 1.f;
    alpha = ps * a * s1 / den;
    beta = ps * bb / den;
    nprev = fminf(nout, MAXN);
}
__device__ __forceinline__ unsigned fenc(float f) {
    unsigned b = __float_as_uint(f);
    return (b & 0x80000000u) ? ~b : (b | 0x80000000u);
}
__device__ __forceinline__ float fdec(unsigned u) {
    return __uint_as_float((u & 0x80000000u) ? (u & 0x7fffffffu) : ~u);
}
__device__ __forceinline__ float lrelu(float x) { return x > 0.f ? x : SLOPE * x; }
__device__ __forceinline__ float tf32r(float x) {
    uint32_t u;
    asm("cvt.rna.tf32.f32 %0, %1;" : "=r"(u) : "f"(x));
    return __uint_as_float(u);
}
__device__ __forceinline__ uint32_t smem_u32(const void* p) {
    uint32_t a;
    asm("{ .reg .u64 t; cvta.to.shared.u64 t, %1; cvt.u32.u64 %0, t; }" : "=r"(a) : "l"(p));
    return a;
}
__device__ __forceinline__ void mma_tf32(float* d, const uint32_t* a, const uint32_t* b) {
    asm volatile(
        "mma.sync.aligned.m16n8k8.row.col.f32.tf32.tf32.f32 "
        "{%0,%1,%2,%3}, {%4,%5,%6,%7}, {%8,%9}, {%0,%1,%2,%3};"
        : "+f"(d[0]), "+f"(d[1]), "+f"(d[2]), "+f"(d[3])
        : "r"(a[0]), "r"(a[1]), "r"(a[2]), "r"(a[3]), "r"(b[0]), "r"(b[1]));
}

// ---------------- k_small: hb vectors + ztf ----------------------------------
__global__ void k_small(const float* __restrict__ bq, const float* __restrict__ bk,
                        const float* __restrict__ bv, const float* __restrict__ bo,
                        const float* __restrict__ tb) {
    int w = threadIdx.x >> 5, l = threadIdx.x & 31;
    if (w < 5) {
        const float* bp = (w == 0) ? bq : (w == 1) ? bk : (w == 2) ? bv : (w == 3) ? bo : tb;
        float v[4]; float ss = 0.f;
#pragma unroll
        for (int m = 0; m < 4; ++m) {
            int o = l + 32 * m;
            float x = (o < DOUT) ? bp[o] : 0.f;
            if (w == 4) x = cosf(x);
            v[m] = (o < DOUT) ? x : 0.f;
            ss += v[m] * v[m];
        }
        ss = wsum32(ss);
        float s, en; enc_scale(ss, s, en);
#pragma unroll
        for (int m = 0; m < 4; ++m) {
            int o = l + 32 * m;
            if (o < DOUT) { if (w < 4) g_hb[w * DOUT + o] = v[m] * s; else g_ztf[o] = v[m] * s; }
        }
        if (l == 0) { if (w < 4) g_hb2[w] = en * en; else g_ztf_e2 = en * en; }
    }
}

// ---------------- k_bfrag: Wk/Wv -> fragment layout, 48-feat half-chunks -----
__global__ void k_bfrag(const float* __restrict__ Wk, const float* __restrict__ Wv) {
    int i = blockIdx.x * blockDim.x + threadIdx.x;
    if (i >= 8 * 12288) return;
    int hc = i / 12288, j = i % 12288;
    int nm = j / 48, kfl = j % 48;
    int mm = nm >> 7, n = nm & 127;
    int kf = hc * 48 + kfl;
    float v = 0.f;
    if (n < 100 && kf < NKV) v = (mm ? Wv : Wk)[n * NKV + kf];
    int ksl = kfl >> 3, kc8 = kfl & 7;
    int lane_t = ((n & 7) << 2) | (kc8 & 3);
    int ii = kc8 >> 2;
    g_Bfrag[hc * 12288 + ((((mm << 4) | (n >> 3)) * 6 + ksl) * 32 + lane_t) * 2 + ii] = tf32r(v);
}

// ---------------- k1: per-dst encode + Q projection (2 CTAs/SM) --------------
#define WSP 105
__global__ void __launch_bounds__(256) k1_dst(const float* __restrict__ dst_h,
                                              const float* __restrict__ Wq, int D) {
    extern __shared__ float sm[];
    float* Ws = sm;               // [200][105] -> reused as M [32][104]
    float* Xs = sm + 200 * WSP;   // [32][200]
    __shared__ float s_xn[32];
    int t = threadIdx.x, w = t >> 5, l = t & 31;
    int rbase = blockIdx.x * 32;
    float ztf_e2 = g_ztf_e2;
    for (int i = 0; i < 4; ++i) {
        int r = w * 4 + i, gr = rbase + r;
        float* xr = Xs + r * 200;
        if (gr < D) {
            const float* dr = dst_h + (size_t)gr * D_NODE;
            float v[4]; float ss = 0.f;
#pragma unroll
            for (int m = 0; m < 4; ++m) { int o = l + 32 * m; v[m] = (o < 100) ? dr[o] : 0.f; ss += v[m] * v[m]; }
            ss = wsum32(ss);
            float s, en; enc_scale(ss, s, en);
#pragma unroll
            for (int m = 0; m < 4; ++m) {
                int o = l + 32 * m;
                if (o < 100) {
                    float h = v[m] * s;
                    xr[o] = h; xr[100 + o] = g_ztf[o];
                    g_dsthyp[(size_t)gr * 100 + o] = h;
                }
            }
            if (l == 0) s_xn[r] = fmaxf(sqrtf(en * en + ztf_e2), MINN);
        } else {
            for (int o = l; o < 200; o += 32) xr[o] = 0.f;
            if (l == 0) s_xn[r] = MINN;
        }
    }
    for (int i = t; i < 5 * 200; i += 256) { int o = 100 + i / 200, k = i % 200; Ws[k * WSP + o] = 0.f; }
    for (int i = t; i < 100 * 200; i += 256) { int o = i / 200, k = i % 200; Ws[k * WSP + o] = Wq[i]; }
    __syncthreads();
    int oc = t & 127, g = t >> 7;
    int ocw = (oc < WSP) ? oc : 0;
    float acc[16];
#pragma unroll
    for (int rr = 0; rr < 16; ++rr) acc[rr] = 0.f;
    for (int k = 0; k < 200; ++k) {
        float wv = Ws[k * WSP + ocw];
#pragma unroll
        for (int rr = 0; rr < 16; ++rr) acc[rr] = fmaf(Xs[(g * 16 + rr) * 200 + k], wv, acc[rr]);
    }
    __syncthreads();
    float* Ms = Ws;
    if (oc < 100) {
#pragma unroll
        for (int rr = 0; rr < 16; ++rr) Ms[(g * 16 + rr) * 104 + oc] = acc[rr];
    }
    __syncthreads();
    float hb2 = g_hb2[0];
    for (int i = 0; i < 4; ++i) {
        int r = w * 4 + i, gr = rbase + r;
        if (gr >= D) continue;
        float mv[4], hv[4]; float pn = 0.f, pd = 0.f;
#pragma unroll
        for (int m = 0; m < 4; ++m) {
            int o = l + 32 * m;
            float a = (o < 100) ? Ms[r * 104 + o] : 0.f;
            float h = (o < 100) ? g_hb[o] : 0.f;
            mv[m] = a; hv[m] = h; pn += a * a; pd += a * h;
        }
        pn = wsum32(pn); pd = wsum32(pd);
        float alpha, beta, np;
        hyp_ab(pn, s_xn[r], pd, hb2, alpha, beta, np);
#pragma unroll
        for (int m = 0; m < 4; ++m) {
            int o = l + 32 * m;
            if (o < 100) g_Qd[(size_t)gr * 100 + o] = alpha * mv[m] + beta * hv[m];
        }
    }
}

// ---------------- k2: mma.sync tf32 + cp.async double-buffered B -------------
#define TE 64
__device__ __forceinline__ void xs_store(float* Xs, int e, int f, float v) {
    int mt = e >> 4, r = e & 15, ks = f >> 3, c = f & 7;
    int lane_t = ((r & 7) << 2) | (c & 3);
    int ii = ((c >> 2) << 1) | (r >> 3);
    Xs[(((mt * 48 + ks) << 5) + lane_t) * 4 + ii] = tf32r(v);
}
__global__ void __launch_bounds__(512) k2_edge(
    const float* __restrict__ neigh, const float* __restrict__ edgef,
    const float* __restrict__ dtp, const int* __restrict__ edst,
    const float* __restrict__ tw, const float* __restrict__ tb, int E) {
    extern __shared__ float sm[];
    float* Xs = sm;            // 24576 floats (96 KB)
    float* Bs = sm + 24576;    // 2 x 12288 floats (96 KB ring)
    __shared__ float s_xn[TE];
    __shared__ int   s_dst[TE];
    __shared__ float s_hbk[DOUT], s_hbv[DOUT];
    __shared__ float s_hb2k, s_hb2v;
    int t = threadIdx.x, w = t >> 5, l = t & 31;
    int base = blockIdx.x * TE;
    uint32_t bs_addr = smem_u32(Bs);

    // kick off prefetch of half-chunk 0 into buffer 0 (overlaps with encode)
    {
        const float* src = g_Bfrag + t * 4;
        uint32_t dst = bs_addr + t * 16;
#pragma unroll
        for (int i2 = 0; i2 < 6; ++i2)
            asm volatile("cp.async.cg.shared.global [%0], [%1], 16;"
                         :: "r"(dst + i2 * 8192), "l"(src + i2 * 2048) : "memory");
        asm volatile("cp.async.commit_group;" ::: "memory");
    }

    // Phase A: encode 4 edges per warp into A-fragment layout
    for (int i = 0; i < 4; ++i) {
        int e = w * 4 + i, ge = base + e;
        if (ge < E) {
            float ss, s, e1, e2, e3;
            const float* nr = neigh + (size_t)ge * D_NODE;
            float v[4]; ss = 0.f;
#pragma unroll
            for (int m = 0; m < 4; ++m) { int o = l + 32 * m; v[m] = (o < 100) ? nr[o] : 0.f; ss += v[m] * v[m]; }
            ss = wsum32(ss); enc_scale(ss, s, e1);
#pragma unroll
            for (int m = 0; m < 4; ++m) { int o = l + 32 * m; if (o < 100) xs_store(Xs, e, o, v[m] * s); }
            const float* er2 = edgef + (size_t)ge * D_EDGE;
            float u[6]; ss = 0.f;
#pragma unroll
            for (int m = 0; m < 6; ++m) { int o = l + 32 * m; u[m] = (o < 172) ? er2[o] : 0.f; ss += u[m] * u[m]; }
            ss = wsum32(ss); enc_scale(ss, s, e2);
#pragma unroll
            for (int m = 0; m < 6; ++m) { int o = l + 32 * m; if (o < 172) xs_store(Xs, e, 100 + o, u[m] * s); }
            float dtv = dtp[ge];
            float cc[4]; ss = 0.f;
#pragma unroll
            for (int m = 0; m < 4; ++m) {
                int o = l + 32 * m;
                float c = (o < 100) ? __cosf(fmaf(dtv, tw[o], tb[o])) : 0.f;
                cc[m] = c; ss += c * c;
            }
            ss = wsum32(ss); enc_scale(ss, s, e3);
#pragma unroll
            for (int m = 0; m < 4; ++m) { int o = l + 32 * m; if (o < 100) xs_store(Xs, e, 272 + o, cc[m] * s); }
            if (l < 12) xs_store(Xs, e, 372 + l, 0.f);
            if (l == 0) { s_xn[e] = fmaxf(sqrtf(e1 * e1 + e2 * e2 + e3 * e3), MINN); s_dst[e] = edst[ge]; }
        } else {
            for (int o = l; o < 384; o += 32) xs_store(Xs, e, o, 0.f);
            if (l == 0) { s_xn[e] = MINN; s_dst[e] = 0; }
        }
    }
    for (int o = t; o < DOUT; o += 512) { s_hbk[o] = g_hb[1 * DOUT + o]; s_hbv[o] = g_hb[2 * DOUT + o]; }
    if (t == 0) { s_hb2k = g_hb2[1]; s_hb2v = g_hb2[2]; }

    int mat = w >> 3, mg = (w >> 2) & 1, ng = w & 3;
    float acc[2][4][4];
#pragma unroll
    for (int a = 0; a < 2; ++a)
#pragma unroll
        for (int b = 0; b < 4; ++b)
#pragma unroll
            for (int cxx = 0; cxx < 4; ++cxx) acc[a][b][cxx] = 0.f;

    for (int hc = 0; hc < 8; ++hc) {
        if (hc < 7) {
            const float* src = g_Bfrag + (hc + 1) * 12288 + t * 4;
            uint32_t dst = bs_addr + ((hc + 1) & 1) * 49152 + t * 16;
#pragma unroll
            for (int i2 = 0; i2 < 6; ++i2)
                asm volatile("cp.async.cg.shared.global [%0], [%1], 16;"
                             :: "r"(dst + i2 * 8192), "l"(src + i2 * 2048) : "memory");
            asm volatile("cp.async.commit_group;" ::: "memory");
            asm volatile("cp.async.wait_group 1;" ::: "memory");
        } else {
            asm volatile("cp.async.wait_group 0;" ::: "memory");
        }
        __syncthreads();   // buffer hc ready across all threads; prior reads done
        const float* Bb = Bs + (hc & 1) * 12288;
#pragma unroll
        for (int ksl = 0; ksl < 6; ++ksl) {
            int ks = hc * 6 + ksl;
            uint32_t a0[4], a1[4];
            *(float4*)a0 = *(const float4*)(Xs + (((2 * mg) * 48 + ks) * 32 + l) * 4);
            *(float4*)a1 = *(const float4*)(Xs + (((2 * mg + 1) * 48 + ks) * 32 + l) * 4);
#pragma unroll
            for (int nt4 = 0; nt4 < 4; ++nt4) {
                int nt = ng * 4 + nt4;
                uint32_t b[2];
                *(float2*)b = *(const float2*)(Bb + (((mat * 16 + nt) * 6 + ksl) * 32 + l) * 2);
                mma_tf32(acc[0][nt4], a0, b);
                mma_tf32(acc[1][nt4], a1, b);
            }
        }
        __syncthreads();   // reads of this buffer done before it is overwritten
    }
    float* Kt = Xs;               // [64][104]
    float* Vt = Xs + TE * 104;    // [64][104]
#pragma unroll
    for (int mi = 0; mi < 2; ++mi) {
        int r0 = (2 * mg + mi) * 16 + (l >> 2);
        float* dst = mat ? Vt : Kt;
#pragma unroll
        for (int nt4 = 0; nt4 < 4; ++nt4) {
            int ncol = ng * 32 + nt4 * 8 + (l & 3) * 2;
            if (ncol < 100) {
                dst[r0 * 104 + ncol]           = acc[mi][nt4][0];
                dst[r0 * 104 + ncol + 1]       = acc[mi][nt4][1];
                dst[(r0 + 8) * 104 + ncol]     = acc[mi][nt4][2];
                dst[(r0 + 8) * 104 + ncol + 1] = acc[mi][nt4][3];
            }
        }
    }
    __syncthreads();

    float hb2k = s_hb2k, hb2v = s_hb2v;
    for (int i = 0; i < 4; ++i) {
        int e = w * 4 + i;
        float pnk = 0.f, pdk = 0.f, pnv = 0.f, pdv = 0.f;
        for (int o = l; o < DOUT; o += 32) {
            float kv = Kt[e * 104 + o], vv = Vt[e * 104 + o];
            pnk += kv * kv; pdk += kv * s_hbk[o];
            pnv += vv * vv; pdv += vv * s_hbv[o];
        }
        pnk = wsum32(pnk); pdk = wsum32(pdk);
        pnv = wsum32(pnv); pdv = wsum32(pdv);
        float alK, beK, alV, beV, np;
        hyp_ab(pnk, s_xn[e], pdk, hb2k, alK, beK, np);
        hyp_ab(pnv, s_xn[e], pdv, hb2v, alV, beV, np);
        for (int o = l; o < DOUT; o += 32) {
            Kt[e * 104 + o] = alK * Kt[e * 104 + o] + beK * s_hbk[o];
            Vt[e * 104 + o] = alV * Vt[e * 104 + o] + beV * s_hbv[o];
        }
    }
    __syncthreads();

    for (int i = 0; i < 4; ++i) {
        int e = w * 4 + i, ge = base + e;
        if (ge >= E) continue;
        int dv = s_dst[e];
        const float* q = g_Qd + (size_t)dv * DOUT;
        float s0 = 0.f, s1v = 0.f;
        for (int o = l; o < DOUT; o += 32) {
            float p = q[o] * Kt[e * 104 + o];
            if (o < 50) s0 += p; else s1v += p;
        }
        s0 = wsum32(s0); s1v = wsum32(s1v);
        if (l == 0) {
            float r0 = lrelu(s0), r1 = lrelu(s1v);
            g_scores[2 * ge] = r0; g_scores[2 * ge + 1] = r1;
            atomicMax(&g_smax[2 * dv], fenc(r0));
            atomicMax(&g_smax[2 * dv + 1], fenc(r1));
        }
    }
    for (int i = t; i < TE * 25; i += 512) {
        int e = i / 25, c4 = i % 25;
        int ge = base + e;
        if (ge < E) {
            float4 v = *(const float4*)(Vt + e * 104 + c4 * 4);
            *(float4*)(g_V + (size_t)ge * DOUT + c4 * 4) = v;
        }
    }
}

// ---------------- k3: exp + segment-sum + UNNORMALIZED scatter-aggregate -----
__global__ void k3_agg(const int* __restrict__ edst, int E) {
    int gw = (blockIdx.x * blockDim.x + threadIdx.x) >> 5;
    int l = threadIdx.x & 31;
    if (gw >= E) return;
    int d = edst[gw];
    float z0 = 0.f, z1 = 0.f;
    if (l == 0) {
        z0 = __expf(g_scores[2 * gw] - fdec(g_smax[2 * d]));
        z1 = __expf(g_scores[2 * gw + 1] - fdec(g_smax[2 * d + 1]));
        atomicAdd(&g_ssum[2 * d], z0);
        atomicAdd(&g_ssum[2 * d + 1], z1);
    }
    z0 = __shfl_sync(0xffffffffu, z0, 0);
    z1 = __shfl_sync(0xffffffffu, z1, 0);
    if (l < 25) {
        const float4* vr = (const float4*)(g_V + (size_t)gw * DOUT);
        float4 v = vr[l];
        int c0 = 4 * l;
        float4 r;
        r.x = v.x * (c0 + 0 < 50 ? z0 : z1);
        r.y = v.y * (c0 + 1 < 50 ? z0 : z1);
        r.z = v.z * (c0 + 2 < 50 ? z0 : z1);
        r.w = v.w * (c0 + 3 < 50 ? z0 : z1);
        float* hp = g_hagg + (size_t)d * DOUT + c0;
        asm volatile("red.global.add.v4.f32 [%0], {%1, %2, %3, %4};"
                     :: "l"(hp), "f"(r.x), "f"(r.y), "f"(r.z), "f"(r.w) : "memory");
    }
}

// ---------------- k5: normalize + O projection + HypAct + LayerNorm ----------
__global__ void __launch_bounds__(256) k5_final(const float* __restrict__ Wo,
                                                const float* __restrict__ lng,
                                                const float* __restrict__ lnb,
                                                float* __restrict__ out, int D) {
    extern __shared__ float sm[];
    float* Ws = sm;               // [200][105] -> reused as M [32][104]
    float* Xs = sm + 200 * WSP;
    __shared__ float s_xn[32];
    int t = threadIdx.x, w = t >> 5, l = t & 31;
    int rbase = blockIdx.x * 32;
    for (int i = 0; i < 4; ++i) {
        int r = w * 4 + i, gr = rbase + r;
        float* xr = Xs + r * 200;
        if (gr < D) {
            const float* ha = g_hagg + (size_t)gr * DOUT;
            const float* dh = g_dsthyp + (size_t)gr * D_NODE;
            float inv0 = 1.f / fmaxf(g_ssum[2 * gr], MINN);
            float inv1 = 1.f / fmaxf(g_ssum[2 * gr + 1], MINN);
            float ss = 0.f;
#pragma unroll
            for (int m = 0; m < 4; ++m) {
                int o = l + 32 * m;
                float a = (o < 100) ? ha[o] * (o < 50 ? inv0 : inv1) : 0.f;
                float b = (o < 100) ? dh[o] : 0.f;
                if (o < 100) { xr[o] = a; xr[100 + o] = b; }
                ss += a * a + b * b;
            }
            ss = wsum32(ss);
            if (l == 0) s_xn[r] = fmaxf(sqrtf(ss), MINN);
        } else {
            for (int o = l; o < 200; o += 32) xr[o] = 0.f;
            if (l == 0) s_xn[r] = MINN;
        }
    }
    for (int i = t; i < 5 * 200; i += 256) { int o = 100 + i / 200, k = i % 200; Ws[k * WSP + o] = 0.f; }
    for (int i = t; i < 100 * 200; i += 256) { int o = i / 200, k = i % 200; Ws[k * WSP + o] = Wo[i]; }
    __syncthreads();
    int oc = t & 127, g = t >> 7;
    int ocw = (oc < WSP) ? oc : 0;
    float acc[16];
#pragma unroll
    for (int rr = 0; rr < 16; ++rr) acc[rr] = 0.f;
    for (int k = 0; k < 200; ++k) {
        float wv = Ws[k * WSP + ocw];
#pragma unroll
        for (int rr = 0; rr < 16; ++rr) acc[rr] = fmaf(Xs[(g * 16 + rr) * 200 + k], wv, acc[rr]);
    }
    __syncthreads();
    float* Ms = Ws;
    if (oc < 100) {
#pragma unroll
        for (int rr = 0; rr < 16; ++rr) Ms[(g * 16 + rr) * 104 + oc] = acc[rr];
    }
    __syncthreads();
    float hb2 = g_hb2[3];
    for (int i = 0; i < 4; ++i) {
        int r = w * 4 + i, gr = rbase + r;
        if (gr >= D) continue;
        float mv[4], hv[4]; float pn = 0.f, pd = 0.f;
#pragma unroll
        for (int m = 0; m < 4; ++m) {
            int o = l + 32 * m;
            float a = (o < 100) ? Ms[r * 104 + o] : 0.f;
            float h = (o < 100) ? g_hb[3 * DOUT + o] : 0.f;
            mv[m] = a; hv[m] = h; pn += a * a; pd += a * h;
        }
        pn = wsum32(pn); pd = wsum32(pd);
        float alpha, beta, nprev;
        hyp_ab(pn, s_xn[r], pd, hb2, alpha, beta, nprev);
        float lc = artanh_f(nprev) / fmaxf(nprev, MINN);
        float u2v[4]; float uss = 0.f;
#pragma unroll
        for (int m = 0; m < 4; ++m) {
            float u2 = lrelu(lc * (alpha * mv[m] + beta * hv[m]));
            u2v[m] = u2; uss += u2 * u2;
        }
        uss = wsum32(uss);
        float s2, en3; enc_scale(uss, s2, en3);
        float hsc = artanh_f(en3) / fmaxf(en3, MINN) * s2;
        float hvv[4]; float hs = 0.f, hs2 = 0.f;
#pragma unroll
        for (int m = 0; m < 4; ++m) {
            int o = l + 32 * m;
            float h = hsc * u2v[m];
            hvv[m] = h;
            if (o < 100) { hs += h; hs2 += h * h; }
        }
        hs = wsum32(hs); hs2 = wsum32(hs2);
        float mu = hs * 0.01f;
        float var = hs2 * 0.01f - mu * mu;
        float inv = rsqrtf(var + 1e-5f);
#pragma unroll
        for (int m = 0; m < 4; ++m) {
            int o = l + 32 * m;
            if (o < 100) out[(size_t)gr * 100 + o] = (hvv[m] - mu) * inv * lng[o] + lnb[o];
        }
    }
}

extern "C" void kernel_launch(void* const* d_in, const int* in_sizes, int n_in,
                              void* d_out, int out_size) {
    const float* dst_h = (const float*)d_in[0];
    const float* neigh = (const float*)d_in[1];
    const float* edgef = (const float*)d_in[2];
    const float* dtp   = (const float*)d_in[3];
    const int*   edst  = (const int*)d_in[4];
    const float* Wq = (const float*)d_in[5];
    const float* bq = (const float*)d_in[6];
    const float* Wk = (const float*)d_in[7];
    const float* bk = (const float*)d_in[8];
    const float* Wv = (const float*)d_in[9];
    const float* bv = (const float*)d_in[10];
    const float* Wo = (const float*)d_in[11];
    const float* bo = (const float*)d_in[12];
    const float* tw = (const float*)d_in[13];
    const float* tb = (const float*)d_in[14];
    const float* lng = (const float*)d_in[15];
    const float* lnb = (const float*)d_in[16];
    float* out = (float*)d_out;
    int D = in_sizes[0] / D_NODE;
    int E = in_sizes[3];

    void *p_hagg = nullptr, *p_ssum = nullptr, *p_smax = nullptr;
    cudaGetSymbolAddress(&p_hagg, g_hagg);
    cudaGetSymbolAddress(&p_ssum, g_ssum);
    cudaGetSymbolAddress(&p_smax, g_smax);
    cudaMemsetAsync(p_hagg, 0, (size_t)D * DOUT * sizeof(float));
    cudaMemsetAsync(p_ssum, 0, (size_t)2 * D * sizeof(float));
    cudaMemsetAsync(p_smax, 0, (size_t)2 * D * sizeof(unsigned));

    size_t smem1 = (200 * WSP + 32 * 200) * sizeof(float);   // 109600
    size_t smem2 = (24576 + 2 * 12288) * sizeof(float);      // 196608
    cudaFuncSetAttribute(k1_dst,   cudaFuncAttributeMaxDynamicSharedMemorySize, (int)smem1);
    cudaFuncSetAttribute(k5_final, cudaFuncAttributeMaxDynamicSharedMemorySize, (int)smem1);
    cudaFuncSetAttribute(k2_edge,  cudaFuncAttributeMaxDynamicSharedMemorySize, (int)smem2);

    k_small<<<1, 160>>>(bq, bk, bv, bo, tb);
    k_bfrag<<<(8 * 12288 + 255) / 256, 256>>>(Wk, Wv);
    k1_dst<<<(D + 31) / 32, 256, smem1>>>(dst_h, Wq, D);
    k2_edge<<<(E + TE - 1) / TE, 512, smem2>>>(neigh, edgef, dtp, edst, tw, tb, E);
    k3_agg<<<(E + 7) / 8, 256>>>(edst, E);
    k5_final<<<(D + 31) / 32, 256, smem1>>>(Wo, lng, lnb, out, D);
}

// round 14
// speedup vs baseline: 2.1588x; 1.4911x over previous
#include <cuda_runtime.h>
#include <math.h>
#include <stdint.h>

#define D_NODE 100
#define D_EDGE 172
#define D_TIME 100
#define NKV    372
#define DOUT   100
#define EMAX   320000
#define DMAX   20000
#define MINN   1e-15f
#define MAXN   0.996f
#define SLOPE  0.2f

__device__ float    g_Qd[DMAX * DOUT];
__device__ float    g_dsthyp[DMAX * D_NODE];
__device__ float    g_V[(size_t)EMAX * DOUT];
__device__ float    g_scores[EMAX * 2];
__device__ unsigned g_smax[DMAX * 2];
__device__ float    g_ssum[DMAX * 2];
__device__ float    g_hagg[DMAX * DOUT];
__device__ float    g_hb[4 * DOUT];
__device__ float    g_hb2[4];
__device__ float    g_ztf[D_TIME];
__device__ float    g_ztf_e2;
__device__ __align__(16) float g_Bfrag[8 * 12288];  // 8 half-chunks, fragment layout

__device__ __forceinline__ float wsum32(float v) {
#pragma unroll
    for (int m = 16; m; m >>= 1) v += __shfl_xor_sync(0xffffffffu, v, m);
    return v;
}
__device__ __forceinline__ float artanh_f(float x) {
    x = fminf(fmaxf(x, -1.0f + 1e-7f), 1.0f - 1e-7f);
    return 0.5f * (log1pf(x) - log1pf(-x));
}
__device__ __forceinline__ void enc_scale(float ss, float& s, float& en) {
    float n = sqrtf(ss), nn = fmaxf(n, MINN);
    float t = tanhf(nn);
    en = fminf(t, MAXN);
    s = en / nn;
}
__device__ __forceinline__ void hyp_ab(float mxn2, float xn, float dot_mh, float hb2,
                                       float& alpha, float& beta, float& nprev) {
    float mxn = fmaxf(sqrtf(mxn2), MINN);
    float t = tanhf(mxn / xn * artanh_f(xn));
    float nres = fminf(t, MAXN);
    float s1 = nres / mxn;
    float x2 = nres * nres;
    float xy = s1 * dot_mh;
    float a = 1.f + 2.f * xy + hb2;
    float bb = 1.f - x2;
    float den = fmaxf(1.f + 2.f * xy + x2 * hb2, MINN);
    float n2 = fmaxf(a * a * x2 + 2.f * a * bb * xy + bb * bb * hb2, 0.f);
    float nout = sqrtf(n2) / den;
    float ps = nout > MAXN ? MAXN / nout : 1.f;
    alpha = ps * a * s1 / den;
    beta = ps * bb / den;
    nprev = fminf(nout, MAXN);
}
__device__ __forceinline__ unsigned fenc(float f) {
    unsigned b = __float_as_uint(f);
    return (b & 0x80000000u) ? ~b : (b | 0x80000000u);
}
__device__ __forceinline__ float fdec(unsigned u) {
    return __uint_as_float((u & 0x80000000u) ? (u & 0x7fffffffu) : ~u);
}
__device__ __forceinline__ float lrelu(float x) { return x > 0.f ? x : SLOPE * x; }
__device__ __forceinline__ float tf32r(float x) {
    uint32_t u;
    asm("cvt.rna.tf32.f32 %0, %1;" : "=r"(u) : "f"(x));
    return __uint_as_float(u);
}
__device__ __forceinline__ void mma_tf32(float* d, const uint32_t* a, const uint32_t* b) {
    asm volatile(
        "mma.sync.aligned.m16n8k8.row.col.f32.tf32.tf32.f32 "
        "{%0,%1,%2,%3}, {%4,%5,%6,%7}, {%8,%9}, {%0,%1,%2,%3};"
        : "+f"(d[0]), "+f"(d[1]), "+f"(d[2]), "+f"(d[3])
        : "r"(a[0]), "r"(a[1]), "r"(a[2]), "r"(a[3]), "r"(b[0]), "r"(b[1]));
}

// ---------------- k_small: hb vectors + ztf ----------------------------------
__global__ void k_small(const float* __restrict__ bq, const float* __restrict__ bk,
                        const float* __restrict__ bv, const float* __restrict__ bo,
                        const float* __restrict__ tb) {
    int w = threadIdx.x >> 5, l = threadIdx.x & 31;
    if (w < 5) {
        const float* bp = (w == 0) ? bq : (w == 1) ? bk : (w == 2) ? bv : (w == 3) ? bo : tb;
        float v[4]; float ss = 0.f;
#pragma unroll
        for (int m = 0; m < 4; ++m) {
            int o = l + 32 * m;
            float x = (o < DOUT) ? bp[o] : 0.f;
            if (w == 4) x = cosf(x);
            v[m] = (o < DOUT) ? x : 0.f;
            ss += v[m] * v[m];
        }
        ss = wsum32(ss);
        float s, en; enc_scale(ss, s, en);
#pragma unroll
        for (int m = 0; m < 4; ++m) {
            int o = l + 32 * m;
            if (o < DOUT) { if (w < 4) g_hb[w * DOUT + o] = v[m] * s; else g_ztf[o] = v[m] * s; }
        }
        if (l == 0) { if (w < 4) g_hb2[w] = en * en; else g_ztf_e2 = en * en; }
    }
}

// ---------------- k_bfrag: Wk/Wv -> fragment layout, 48-feat half-chunks -----
__global__ void k_bfrag(const float* __restrict__ Wk, const float* __restrict__ Wv) {
    int i = blockIdx.x * blockDim.x + threadIdx.x;
    if (i >= 8 * 12288) return;
    int hc = i / 12288, j = i % 12288;
    int nm = j / 48, kfl = j % 48;
    int mm = nm >> 7, n = nm & 127;
    int kf = hc * 48 + kfl;
    float v = 0.f;
    if (n < 100 && kf < NKV) v = (mm ? Wv : Wk)[n * NKV + kf];
    int ksl = kfl >> 3, kc8 = kfl & 7;
    int lane_t = ((n & 7) << 2) | (kc8 & 3);
    int ii = kc8 >> 2;
    g_Bfrag[hc * 12288 + ((((mm << 4) | (n >> 3)) * 6 + ksl) * 32 + lane_t) * 2 + ii] = tf32r(v);
}

// ---------------- k1: per-dst encode + Q projection (2 CTAs/SM) --------------
#define WSP 105
__global__ void __launch_bounds__(256) k1_dst(const float* __restrict__ dst_h,
                                              const float* __restrict__ Wq, int D) {
    extern __shared__ float sm[];
    float* Ws = sm;               // [200][105] -> reused as M [32][104]
    float* Xs = sm + 200 * WSP;   // [32][200]
    __shared__ float s_xn[32];
    int t = threadIdx.x, w = t >> 5, l = t & 31;
    int rbase = blockIdx.x * 32;
    float ztf_e2 = g_ztf_e2;
    for (int i = 0; i < 4; ++i) {
        int r = w * 4 + i, gr = rbase + r;
        float* xr = Xs + r * 200;
        if (gr < D) {
            const float* dr = dst_h + (size_t)gr * D_NODE;
            float v[4]; float ss = 0.f;
#pragma unroll
            for (int m = 0; m < 4; ++m) { int o = l + 32 * m; v[m] = (o < 100) ? dr[o] : 0.f; ss += v[m] * v[m]; }
            ss = wsum32(ss);
            float s, en; enc_scale(ss, s, en);
#pragma unroll
            for (int m = 0; m < 4; ++m) {
                int o = l + 32 * m;
                if (o < 100) {
                    float h = v[m] * s;
                    xr[o] = h; xr[100 + o] = g_ztf[o];
                    g_dsthyp[(size_t)gr * 100 + o] = h;
                }
            }
            if (l == 0) s_xn[r] = fmaxf(sqrtf(en * en + ztf_e2), MINN);
        } else {
            for (int o = l; o < 200; o += 32) xr[o] = 0.f;
            if (l == 0) s_xn[r] = MINN;
        }
    }
    for (int i = t; i < 5 * 200; i += 256) { int o = 100 + i / 200, k = i % 200; Ws[k * WSP + o] = 0.f; }
    for (int i = t; i < 100 * 200; i += 256) { int o = i / 200, k = i % 200; Ws[k * WSP + o] = Wq[i]; }
    __syncthreads();
    int oc = t & 127, g = t >> 7;
    int ocw = (oc < WSP) ? oc : 0;
    float acc[16];
#pragma unroll
    for (int rr = 0; rr < 16; ++rr) acc[rr] = 0.f;
    for (int k = 0; k < 200; ++k) {
        float wv = Ws[k * WSP + ocw];
#pragma unroll
        for (int rr = 0; rr < 16; ++rr) acc[rr] = fmaf(Xs[(g * 16 + rr) * 200 + k], wv, acc[rr]);
    }
    __syncthreads();
    float* Ms = Ws;
    if (oc < 100) {
#pragma unroll
        for (int rr = 0; rr < 16; ++rr) Ms[(g * 16 + rr) * 104 + oc] = acc[rr];
    }
    __syncthreads();
    float hb2 = g_hb2[0];
    for (int i = 0; i < 4; ++i) {
        int r = w * 4 + i, gr = rbase + r;
        if (gr >= D) continue;
        float mv[4], hv[4]; float pn = 0.f, pd = 0.f;
#pragma unroll
        for (int m = 0; m < 4; ++m) {
            int o = l + 32 * m;
            float a = (o < 100) ? Ms[r * 104 + o] : 0.f;
            float h = (o < 100) ? g_hb[o] : 0.f;
            mv[m] = a; hv[m] = h; pn += a * a; pd += a * h;
        }
        pn = wsum32(pn); pd = wsum32(pd);
        float alpha, beta, np;
        hyp_ab(pn, s_xn[r], pd, hb2, alpha, beta, np);
#pragma unroll
        for (int m = 0; m < 4; ++m) {
            int o = l + 32 * m;
            if (o < 100) g_Qd[(size_t)gr * 100 + o] = alpha * mv[m] + beta * hv[m];
        }
    }
}

// ---------------- k2: mma.sync tf32, B direct from L2, 2 CTAs/SM -------------
#define TE 64
__device__ __forceinline__ void xs_store(float* Xs, int e, int f, float v) {
    int mt = e >> 4, r = e & 15, ks = f >> 3, c = f & 7;
    int lane_t = ((r & 7) << 2) | (c & 3);
    int ii = ((c >> 2) << 1) | (r >> 3);
    Xs[(((mt * 48 + ks) << 5) + lane_t) * 4 + ii] = tf32r(v);
}
__global__ void __launch_bounds__(512, 2) k2_edge(
    const float* __restrict__ neigh, const float* __restrict__ edgef,
    const float* __restrict__ dtp, const int* __restrict__ edst,
    const float* __restrict__ tw, const float* __restrict__ tb, int E) {
    extern __shared__ float sm[];
    float* Xs = sm;            // 24576 floats (96 KB)
    __shared__ float s_xn[TE];
    __shared__ int   s_dst[TE];
    __shared__ float s_hbk[DOUT], s_hbv[DOUT];
    __shared__ float s_hb2k, s_hb2v;
    int t = threadIdx.x, w = t >> 5, l = t & 31;
    int base = blockIdx.x * TE;

    // Phase A: encode 4 edges per warp into A-fragment layout
    for (int i = 0; i < 4; ++i) {
        int e = w * 4 + i, ge = base + e;
        if (ge < E) {
            float ss, s, e1, e2, e3;
            const float* nr = neigh + (size_t)ge * D_NODE;
            float v[4]; ss = 0.f;
#pragma unroll
            for (int m = 0; m < 4; ++m) { int o = l + 32 * m; v[m] = (o < 100) ? nr[o] : 0.f; ss += v[m] * v[m]; }
            ss = wsum32(ss); enc_scale(ss, s, e1);
#pragma unroll
            for (int m = 0; m < 4; ++m) { int o = l + 32 * m; if (o < 100) xs_store(Xs, e, o, v[m] * s); }
            const float* er2 = edgef + (size_t)ge * D_EDGE;
            float u[6]; ss = 0.f;
#pragma unroll
            for (int m = 0; m < 6; ++m) { int o = l + 32 * m; u[m] = (o < 172) ? er2[o] : 0.f; ss += u[m] * u[m]; }
            ss = wsum32(ss); enc_scale(ss, s, e2);
#pragma unroll
            for (int m = 0; m < 6; ++m) { int o = l + 32 * m; if (o < 172) xs_store(Xs, e, 100 + o, u[m] * s); }
            float dtv = dtp[ge];
            float cc[4]; ss = 0.f;
#pragma unroll
            for (int m = 0; m < 4; ++m) {
                int o = l + 32 * m;
                float c = (o < 100) ? __cosf(fmaf(dtv, tw[o], tb[o])) : 0.f;
                cc[m] = c; ss += c * c;
            }
            ss = wsum32(ss); enc_scale(ss, s, e3);
#pragma unroll
            for (int m = 0; m < 4; ++m) { int o = l + 32 * m; if (o < 100) xs_store(Xs, e, 272 + o, cc[m] * s); }
            if (l < 12) xs_store(Xs, e, 372 + l, 0.f);
            if (l == 0) { s_xn[e] = fmaxf(sqrtf(e1 * e1 + e2 * e2 + e3 * e3), MINN); s_dst[e] = edst[ge]; }
        } else {
            for (int o = l; o < 384; o += 32) xs_store(Xs, e, o, 0.f);
            if (l == 0) { s_xn[e] = MINN; s_dst[e] = 0; }
        }
    }
    for (int o = t; o < DOUT; o += 512) { s_hbk[o] = g_hb[1 * DOUT + o]; s_hbv[o] = g_hb[2 * DOUT + o]; }
    if (t == 0) { s_hb2k = g_hb2[1]; s_hb2v = g_hb2[2]; }
    __syncthreads();

    // GEMM: warp = (mat, mgroup of 2 mtiles, ngroup of 4 ntiles)
    // B fragments streamed directly from L2 (same lines for all CTAs).
    int mat = w >> 3, mg = (w >> 2) & 1, ng = w & 3;
    float acc[2][4][4];
#pragma unroll
    for (int a = 0; a < 2; ++a)
#pragma unroll
        for (int b = 0; b < 4; ++b)
#pragma unroll
            for (int cxx = 0; cxx < 4; ++cxx) acc[a][b][cxx] = 0.f;

    // per-warp B base: (mat*16 + ng*4) n-tile, lane l
    const float2* Bg = (const float2*)(g_Bfrag) + ((mat * 16 + ng * 4) * 6) * 32 + l;
    for (int hc = 0; hc < 8; ++hc) {
        const float2* Bh = Bg + hc * 6144;
#pragma unroll
        for (int ksl = 0; ksl < 6; ++ksl) {
            int ks = hc * 6 + ksl;
            uint32_t a0[4], a1[4];
            *(float4*)a0 = *(const float4*)(Xs + (((2 * mg) * 48 + ks) * 32 + l) * 4);
            *(float4*)a1 = *(const float4*)(Xs + (((2 * mg + 1) * 48 + ks) * 32 + l) * 4);
            float2 bf[4];
#pragma unroll
            for (int nt4 = 0; nt4 < 4; ++nt4)
                bf[nt4] = __ldg(Bh + (nt4 * 6 + ksl) * 32);
#pragma unroll
            for (int nt4 = 0; nt4 < 4; ++nt4) {
                uint32_t b[2];
                *(float2*)b = bf[nt4];
                mma_tf32(acc[0][nt4], a0, b);
                mma_tf32(acc[1][nt4], a1, b);
            }
        }
    }
    __syncthreads();   // all Xs reads done; reuse as Kt/Vt
    float* Kt = Xs;               // [64][104]
    float* Vt = Xs + TE * 104;    // [64][104]
#pragma unroll
    for (int mi = 0; mi < 2; ++mi) {
        int r0 = (2 * mg + mi) * 16 + (l >> 2);
        float* dst = mat ? Vt : Kt;
#pragma unroll
        for (int nt4 = 0; nt4 < 4; ++nt4) {
            int ncol = ng * 32 + nt4 * 8 + (l & 3) * 2;
            if (ncol < 100) {
                dst[r0 * 104 + ncol]           = acc[mi][nt4][0];
                dst[r0 * 104 + ncol + 1]       = acc[mi][nt4][1];
                dst[(r0 + 8) * 104 + ncol]     = acc[mi][nt4][2];
                dst[(r0 + 8) * 104 + ncol + 1] = acc[mi][nt4][3];
            }
        }
    }
    __syncthreads();

    float hb2k = s_hb2k, hb2v = s_hb2v;
    for (int i = 0; i < 4; ++i) {
        int e = w * 4 + i;
        float pnk = 0.f, pdk = 0.f, pnv = 0.f, pdv = 0.f;
        for (int o = l; o < DOUT; o += 32) {
            float kv = Kt[e * 104 + o], vv = Vt[e * 104 + o];
            pnk += kv * kv; pdk += kv * s_hbk[o];
            pnv += vv * vv; pdv += vv * s_hbv[o];
        }
        pnk = wsum32(pnk); pdk = wsum32(pdk);
        pnv = wsum32(pnv); pdv = wsum32(pdv);
        float alK, beK, alV, beV, np;
        hyp_ab(pnk, s_xn[e], pdk, hb2k, alK, beK, np);
        hyp_ab(pnv, s_xn[e], pdv, hb2v, alV, beV, np);
        for (int o = l; o < DOUT; o += 32) {
            Kt[e * 104 + o] = alK * Kt[e * 104 + o] + beK * s_hbk[o];
            Vt[e * 104 + o] = alV * Vt[e * 104 + o] + beV * s_hbv[o];
        }
    }
    __syncthreads();

    for (int i = 0; i < 4; ++i) {
        int e = w * 4 + i, ge = base + e;
        if (ge >= E) continue;
        int dv = s_dst[e];
        const float* q = g_Qd + (size_t)dv * DOUT;
        float s0 = 0.f, s1v = 0.f;
        for (int o = l; o < DOUT; o += 32) {
            float p = q[o] * Kt[e * 104 + o];
            if (o < 50) s0 += p; else s1v += p;
        }
        s0 = wsum32(s0); s1v = wsum32(s1v);
        if (l == 0) {
            float r0 = lrelu(s0), r1 = lrelu(s1v);
            g_scores[2 * ge] = r0; g_scores[2 * ge + 1] = r1;
            atomicMax(&g_smax[2 * dv], fenc(r0));
            atomicMax(&g_smax[2 * dv + 1], fenc(r1));
        }
    }
    for (int i = t; i < TE * 25; i += 512) {
        int e = i / 25, c4 = i % 25;
        int ge = base + e;
        if (ge < E) {
            float4 v = *(const float4*)(Vt + e * 104 + c4 * 4);
            *(float4*)(g_V + (size_t)ge * DOUT + c4 * 4) = v;
        }
    }
}

// ---------------- k3: exp + segment-sum + UNNORMALIZED scatter-aggregate -----
__global__ void k3_agg(const int* __restrict__ edst, int E) {
    int gw = (blockIdx.x * blockDim.x + threadIdx.x) >> 5;
    int l = threadIdx.x & 31;
    if (gw >= E) return;
    int d = edst[gw];
    float z0 = 0.f, z1 = 0.f;
    if (l == 0) {
        z0 = __expf(g_scores[2 * gw] - fdec(g_smax[2 * d]));
        z1 = __expf(g_scores[2 * gw + 1] - fdec(g_smax[2 * d + 1]));
        atomicAdd(&g_ssum[2 * d], z0);
        atomicAdd(&g_ssum[2 * d + 1], z1);
    }
    z0 = __shfl_sync(0xffffffffu, z0, 0);
    z1 = __shfl_sync(0xffffffffu, z1, 0);
    if (l < 25) {
        const float4* vr = (const float4*)(g_V + (size_t)gw * DOUT);
        float4 v = vr[l];
        int c0 = 4 * l;
        float4 r;
        r.x = v.x * (c0 + 0 < 50 ? z0 : z1);
        r.y = v.y * (c0 + 1 < 50 ? z0 : z1);
        r.z = v.z * (c0 + 2 < 50 ? z0 : z1);
        r.w = v.w * (c0 + 3 < 50 ? z0 : z1);
        float* hp = g_hagg + (size_t)d * DOUT + c0;
        asm volatile("red.global.add.v4.f32 [%0], {%1, %2, %3, %4};"
                     :: "l"(hp), "f"(r.x), "f"(r.y), "f"(r.z), "f"(r.w) : "memory");
    }
}

// ---------------- k5: normalize + O projection + HypAct + LayerNorm ----------
__global__ void __launch_bounds__(256) k5_final(const float* __restrict__ Wo,
                                                const float* __restrict__ lng,
                                                const float* __restrict__ lnb,
                                                float* __restrict__ out, int D) {
    extern __shared__ float sm[];
    float* Ws = sm;               // [200][105] -> reused as M [32][104]
    float* Xs = sm + 200 * WSP;
    __shared__ float s_xn[32];
    int t = threadIdx.x, w = t >> 5, l = t & 31;
    int rbase = blockIdx.x * 32;
    for (int i = 0; i < 4; ++i) {
        int r = w * 4 + i, gr = rbase + r;
        float* xr = Xs + r * 200;
        if (gr < D) {
            const float* ha = g_hagg + (size_t)gr * DOUT;
            const float* dh = g_dsthyp + (size_t)gr * D_NODE;
            float inv0 = 1.f / fmaxf(g_ssum[2 * gr], MINN);
            float inv1 = 1.f / fmaxf(g_ssum[2 * gr + 1], MINN);
            float ss = 0.f;
#pragma unroll
            for (int m = 0; m < 4; ++m) {
                int o = l + 32 * m;
                float a = (o < 100) ? ha[o] * (o < 50 ? inv0 : inv1) : 0.f;
                float b = (o < 100) ? dh[o] : 0.f;
                if (o < 100) { xr[o] = a; xr[100 + o] = b; }
                ss += a * a + b * b;
            }
            ss = wsum32(ss);
            if (l == 0) s_xn[r] = fmaxf(sqrtf(ss), MINN);
        } else {
            for (int o = l; o < 200; o += 32) xr[o] = 0.f;
            if (l == 0) s_xn[r] = MINN;
        }
    }
    for (int i = t; i < 5 * 200; i += 256) { int o = 100 + i / 200, k = i % 200; Ws[k * WSP + o] = 0.f; }
    for (int i = t; i < 100 * 200; i += 256) { int o = i / 200, k = i % 200; Ws[k * WSP + o] = Wo[i]; }
    __syncthreads();
    int oc = t & 127, g = t >> 7;
    int ocw = (oc < WSP) ? oc : 0;
    float acc[16];
#pragma unroll
    for (int rr = 0; rr < 16; ++rr) acc[rr] = 0.f;
    for (int k = 0; k < 200; ++k) {
        float wv = Ws[k * WSP + ocw];
#pragma unroll
        for (int rr = 0; rr < 16; ++rr) acc[rr] = fmaf(Xs[(g * 16 + rr) * 200 + k], wv, acc[rr]);
    }
    __syncthreads();
    float* Ms = Ws;
    if (oc < 100) {
#pragma unroll
        for (int rr = 0; rr < 16; ++rr) Ms[(g * 16 + rr) * 104 + oc] = acc[rr];
    }
    __syncthreads();
    float hb2 = g_hb2[3];
    for (int i = 0; i < 4; ++i) {
        int r = w * 4 + i, gr = rbase + r;
        if (gr >= D) continue;
        float mv[4], hv[4]; float pn = 0.f, pd = 0.f;
#pragma unroll
        for (int m = 0; m < 4; ++m) {
            int o = l + 32 * m;
            float a = (o < 100) ? Ms[r * 104 + o] : 0.f;
            float h = (o < 100) ? g_hb[3 * DOUT + o] : 0.f;
            mv[m] = a; hv[m] = h; pn += a * a; pd += a * h;
        }
        pn = wsum32(pn); pd = wsum32(pd);
        float alpha, beta, nprev;
        hyp_ab(pn, s_xn[r], pd, hb2, alpha, beta, nprev);
        float lc = artanh_f(nprev) / fmaxf(nprev, MINN);
        float u2v[4]; float uss = 0.f;
#pragma unroll
        for (int m = 0; m < 4; ++m) {
            float u2 = lrelu(lc * (alpha * mv[m] + beta * hv[m]));
            u2v[m] = u2; uss += u2 * u2;
        }
        uss = wsum32(uss);
        float s2, en3; enc_scale(uss, s2, en3);
        float hsc = artanh_f(en3) / fmaxf(en3, MINN) * s2;
        float hvv[4]; float hs = 0.f, hs2 = 0.f;
#pragma unroll
        for (int m = 0; m < 4; ++m) {
            int o = l + 32 * m;
            float h = hsc * u2v[m];
            hvv[m] = h;
            if (o < 100) { hs += h; hs2 += h * h; }
        }
        hs = wsum32(hs); hs2 = wsum32(hs2);
        float mu = hs * 0.01f;
        float var = hs2 * 0.01f - mu * mu;
        float inv = rsqrtf(var + 1e-5f);
#pragma unroll
        for (int m = 0; m < 4; ++m) {
            int o = l + 32 * m;
            if (o < 100) out[(size_t)gr * 100 + o] = (hvv[m] - mu) * inv * lng[o] + lnb[o];
        }
    }
}

extern "C" void kernel_launch(void* const* d_in, const int* in_sizes, int n_in,
                              void* d_out, int out_size) {
    const float* dst_h = (const float*)d_in[0];
    const float* neigh = (const float*)d_in[1];
    const float* edgef = (const float*)d_in[2];
    const float* dtp   = (const float*)d_in[3];
    const int*   edst  = (const int*)d_in[4];
    const float* Wq = (const float*)d_in[5];
    const float* bq = (const float*)d_in[6];
    const float* Wk = (const float*)d_in[7];
    const float* bk = (const float*)d_in[8];
    const float* Wv = (const float*)d_in[9];
    const float* bv = (const float*)d_in[10];
    const float* Wo = (const float*)d_in[11];
    const float* bo = (const float*)d_in[12];
    const float* tw = (const float*)d_in[13];
    const float* tb = (const float*)d_in[14];
    const float* lng = (const float*)d_in[15];
    const float* lnb = (const float*)d_in[16];
    float* out = (float*)d_out;
    int D = in_sizes[0] / D_NODE;
    int E = in_sizes[3];

    void *p_hagg = nullptr, *p_ssum = nullptr, *p_smax = nullptr;
    cudaGetSymbolAddress(&p_hagg, g_hagg);
    cudaGetSymbolAddress(&p_ssum, g_ssum);
    cudaGetSymbolAddress(&p_smax, g_smax);
    cudaMemsetAsync(p_hagg, 0, (size_t)D * DOUT * sizeof(float));
    cudaMemsetAsync(p_ssum, 0, (size_t)2 * D * sizeof(float));
    cudaMemsetAsync(p_smax, 0, (size_t)2 * D * sizeof(unsigned));

    size_t smem1 = (200 * WSP + 32 * 200) * sizeof(float);   // 109600
    size_t smem2 = 24576 * sizeof(float);                    // 98304 -> 2 CTAs/SM
    cudaFuncSetAttribute(k1_dst,   cudaFuncAttributeMaxDynamicSharedMemorySize, (int)smem1);
    cudaFuncSetAttribute(k5_final, cudaFuncAttributeMaxDynamicSharedMemorySize, (int)smem1);
    cudaFuncSetAttribute(k2_edge,  cudaFuncAttributeMaxDynamicSharedMemorySize, (int)smem2);

    k_small<<<1, 160>>>(bq, bk, bv, bo, tb);
    k_bfrag<<<(8 * 12288 + 255) / 256, 256>>>(Wk, Wv);
    k1_dst<<<(D + 31) / 32, 256, smem1>>>(dst_h, Wq, D);
    k2_edge<<<(E + TE - 1) / TE, 512, smem2>>>(neigh, edgef, dtp, edst, tw, tb, E);
    k3_agg<<<(E + 7) / 8, 256>>>(edst, E);
    k5_final<<<(D + 31) / 32, 256, smem1>>>(Wo, lng, lnb, out, D);
}

// round 17
// speedup vs baseline: 2.5174x; 1.1661x over previous
#include <cuda_runtime.h>
#include <math.h>
#include <stdint.h>

#define D_NODE 100
#define D_EDGE 172
#define D_TIME 100
#define NKV    372
#define DOUT   100
#define EMAX   320000
#define DMAX   20000
#define MINN   1e-15f
#define MAXN   0.996f
#define SLOPE  0.2f

__device__ float    g_Qd[DMAX * DOUT];
__device__ float    g_dsthyp[DMAX * D_NODE];
__device__ float    g_V[(size_t)EMAX * DOUT];
__device__ float    g_scores[EMAX * 2];
__device__ unsigned g_smax[DMAX * 2];
__device__ float    g_ssum[DMAX * 2];
__device__ float    g_hagg[DMAX * DOUT];
__device__ float    g_hb[4 * DOUT];
__device__ float    g_hb2[4];
__device__ float    g_ztf[D_TIME];
__device__ float    g_ztf_e2;
__device__ __align__(16) float g_Bfrag[8 * 12288];

__device__ __forceinline__ float wsum32(float v) {
#pragma unroll
    for (int m = 16; m; m >>= 1) v += __shfl_xor_sync(0xffffffffu, v, m);
    return v;
}
__device__ __forceinline__ float artanh_f(float x) {
    x = fminf(fmaxf(x, -1.0f + 1e-7f), 1.0f - 1e-7f);
    return 0.5f * (log1pf(x) - log1pf(-x));
}
__device__ __forceinline__ void enc_scale(float ss, float& s, float& en) {
    float n = sqrtf(ss), nn = fmaxf(n, MINN);
    float t = tanhf(nn);
    en = fminf(t, MAXN);
    s = en / nn;
}
__device__ __forceinline__ void hyp_ab(float mxn2, float xn, float dot_mh, float hb2,
                                       float& alpha, float& beta, float& nprev) {
    float mxn = fmaxf(sqrtf(mxn2), MINN);
    float t = tanhf(mxn / xn * artanh_f(xn));
    float nres = fminf(t, MAXN);
    float s1 = nres / mxn;
    float x2 = nres * nres;
    float xy = s1 * dot_mh;
    float a = 1.f + 2.f * xy + hb2;
    float bb = 1.f - x2;
    float den = fmaxf(1.f + 2.f * xy + x2 * hb2, MINN);
    float n2 = fmaxf(a * a * x2 + 2.f * a * bb * xy + bb * bb * hb2, 0.f);
    float nout = sqrtf(n2) / den;
    float ps = nout > MAXN ? MAXN / nout : 1.f;
    alpha = ps * a * s1 / den;
    beta = ps * bb / den;
    nprev = fminf(nout, MAXN);
}
__device__ __forceinline__ unsigned fenc(float f) {
    unsigned b = __float_as_uint(f);
    return (b & 0x80000000u) ? ~b : (b | 0x80000000u);
}
__device__ __forceinline__ float fdec(unsigned u) {
    return __uint_as_float((u & 0x80000000u) ? (u & 0x7fffffffu) : ~u);
}
__device__ __forceinline__ float lrelu(float x) { return x > 0.f ? x : SLOPE * x; }
__device__ __forceinline__ float tf32r(float x) {
    uint32_t u;
    asm("cvt.rna.tf32.f32 %0, %1;" : "=r"(u) : "f"(x));
    return __uint_as_float(u);
}
__device__ __forceinline__ void mma_tf32(float* d, const uint32_t* a, const uint32_t* b) {
    asm volatile(
        "mma.sync.aligned.m16n8k8.row.col.f32.tf32.tf32.f32 "
        "{%0,%1,%2,%3}, {%4,%5,%6,%7}, {%8,%9}, {%0,%1,%2,%3};"
        : "+f"(d[0]), "+f"(d[1]), "+f"(d[2]), "+f"(d[3])
        : "r"(a[0]), "r"(a[1]), "r"(a[2]), "r"(a[3]), "r"(b[0]), "r"(b[1]));
}

// ---------------- k_small: hb vectors + ztf ----------------------------------
__global__ void k_small(const float* __restrict__ bq, const float* __restrict__ bk,
                        const float* __restrict__ bv, const float* __restrict__ bo,
                        const float* __restrict__ tb) {
    int w = threadIdx.x >> 5, l = threadIdx.x & 31;
    if (w < 5) {
        const float* bp = (w == 0) ? bq : (w == 1) ? bk : (w == 2) ? bv : (w == 3) ? bo : tb;
        float v[4]; float ss = 0.f;
#pragma unroll
        for (int m = 0; m < 4; ++m) {
            int o = l + 32 * m;
            float x = (o < DOUT) ? bp[o] : 0.f;
            if (w == 4) x = cosf(x);
            v[m] = (o < DOUT) ? x : 0.f;
            ss += v[m] * v[m];
        }
        ss = wsum32(ss);
        float s, en; enc_scale(ss, s, en);
#pragma unroll
        for (int m = 0; m < 4; ++m) {
            int o = l + 32 * m;
            if (o < DOUT) { if (w < 4) g_hb[w * DOUT + o] = v[m] * s; else g_ztf[o] = v[m] * s; }
        }
        if (l == 0) { if (w < 4) g_hb2[w] = en * en; else g_ztf_e2 = en * en; }
    }
}

// ---------------- k_bfrag: Wk/Wv -> fragment layout, 48-feat half-chunks -----
__global__ void k_bfrag(const float* __restrict__ Wk, const float* __restrict__ Wv) {
    int i = blockIdx.x * blockDim.x + threadIdx.x;
    if (i >= 8 * 12288) return;
    int hc = i / 12288, j = i % 12288;
    int nm = j / 48, kfl = j % 48;
    int mm = nm >> 7, n = nm & 127;
    int kf = hc * 48 + kfl;
    float v = 0.f;
    if (n < 100 && kf < NKV) v = (mm ? Wv : Wk)[n * NKV + kf];
    int ksl = kfl >> 3, kc8 = kfl & 7;
    int lane_t = ((n & 7) << 2) | (kc8 & 3);
    int ii = kc8 >> 2;
    g_Bfrag[hc * 12288 + ((((mm << 4) | (n >> 3)) * 6 + ksl) * 32 + lane_t) * 2 + ii] = tf32r(v);
}

// ---------------- k1: per-dst encode + Q projection (2 CTAs/SM) --------------
#define WSP 105
__global__ void __launch_bounds__(256) k1_dst(const float* __restrict__ dst_h,
                                              const float* __restrict__ Wq, int D) {
    extern __shared__ float sm[];
    float* Ws = sm;
    float* Xs = sm + 200 * WSP;
    __shared__ float s_xn[32];
    int t = threadIdx.x, w = t >> 5, l = t & 31;
    int rbase = blockIdx.x * 32;
    float ztf_e2 = g_ztf_e2;
    for (int i = 0; i < 4; ++i) {
        int r = w * 4 + i, gr = rbase + r;
        float* xr = Xs + r * 200;
        if (gr < D) {
            const float* dr = dst_h + (size_t)gr * D_NODE;
            float v[4]; float ss = 0.f;
#pragma unroll
            for (int m = 0; m < 4; ++m) { int o = l + 32 * m; v[m] = (o < 100) ? dr[o] : 0.f; ss += v[m] * v[m]; }
            ss = wsum32(ss);
            float s, en; enc_scale(ss, s, en);
#pragma unroll
            for (int m = 0; m < 4; ++m) {
                int o = l + 32 * m;
                if (o < 100) {
                    float h = v[m] * s;
                    xr[o] = h; xr[100 + o] = g_ztf[o];
                    g_dsthyp[(size_t)gr * 100 + o] = h;
                }
            }
            if (l == 0) s_xn[r] = fmaxf(sqrtf(en * en + ztf_e2), MINN);
        } else {
            for (int o = l; o < 200; o += 32) xr[o] = 0.f;
            if (l == 0) s_xn[r] = MINN;
        }
    }
    for (int i = t; i < 5 * 200; i += 256) { int o = 100 + i / 200, k = i % 200; Ws[k * WSP + o] = 0.f; }
    for (int i = t; i < 100 * 200; i += 256) { int o = i / 200, k = i % 200; Ws[k * WSP + o] = Wq[i]; }
    __syncthreads();
    int oc = t & 127, g = t >> 7;
    int ocw = (oc < WSP) ? oc : 0;
    float acc[16];
#pragma unroll
    for (int rr = 0; rr < 16; ++rr) acc[rr] = 0.f;
    for (int k = 0; k < 200; ++k) {
        float wv = Ws[k * WSP + ocw];
#pragma unroll
        for (int rr = 0; rr < 16; ++rr) acc[rr] = fmaf(Xs[(g * 16 + rr) * 200 + k], wv, acc[rr]);
    }
    __syncthreads();
    float* Ms = Ws;
    if (oc < 100) {
#pragma unroll
        for (int rr = 0; rr < 16; ++rr) Ms[(g * 16 + rr) * 104 + oc] = acc[rr];
    }
    __syncthreads();
    float hb2 = g_hb2[0];
    for (int i = 0; i < 4; ++i) {
        int r = w * 4 + i, gr = rbase + r;
        if (gr >= D) continue;
        float mv[4], hv[4]; float pn = 0.f, pd = 0.f;
#pragma unroll
        for (int m = 0; m < 4; ++m) {
            int o = l + 32 * m;
            float a = (o < 100) ? Ms[r * 104 + o] : 0.f;
            float h = (o < 100) ? g_hb[o] : 0.f;
            mv[m] = a; hv[m] = h; pn += a * a; pd += a * h;
        }
        pn = wsum32(pn); pd = wsum32(pd);
        float alpha, beta, np;
        hyp_ab(pn, s_xn[r], pd, hb2, alpha, beta, np);
#pragma unroll
        for (int m = 0; m < 4; ++m) {
            int o = l + 32 * m;
            if (o < 100) g_Qd[(size_t)gr * 100 + o] = alpha * mv[m] + beta * hv[m];
        }
    }
}

// ---------------- k2: mma.sync tf32, reg-level epilogue, 2 CTAs/SM -----------
#define TE 64
__device__ __forceinline__ void xs_store(float* Xs, int e, int f, float v) {
    int mt = e >> 4, r = e & 15, ks = f >> 3, c = f & 7;
    int lane_t = ((r & 7) << 2) | (c & 3);
    int ii = ((c >> 2) << 1) | (r >> 3);
    Xs[(((mt * 48 + ks) << 5) + lane_t) * 4 + ii] = tf32r(v);
}
// affine base: for fixed (e, l, off0), stores go at base + 512*m (m-step = 32 feats)
__device__ __forceinline__ int xs_base(int e, int l, int off0) {
    int mt = e >> 4, r = e & 15;
    int f0 = off0 + l;
    int c = f0 & 7, ks0 = f0 >> 3;
    int lane_t = ((r & 7) << 2) | (c & 3);
    int ii = ((c >> 2) << 1) | (r >> 3);
    return (mt * 48 + ks0) * 128 + lane_t * 4 + ii;
}
__global__ void __launch_bounds__(512, 2) k2_edge(
    const float* __restrict__ neigh, const float* __restrict__ edgef,
    const float* __restrict__ dtp, const int* __restrict__ edst,
    const float* __restrict__ tw, const float* __restrict__ tb, int E) {
    extern __shared__ float sm[];
    float* Xs = sm;            // 24576 floats (96 KB)
    __shared__ float s_xn[TE];
    __shared__ int   s_dst[TE];
    __shared__ float s_hbk[128], s_hbv[128];   // zero-padded to 128
    __shared__ float s_hb2k, s_hb2v;
    __shared__ float s_pnk[TE], s_pdk[TE], s_pnv[TE], s_pdv[TE];
    __shared__ float s_al[2][TE], s_be[2][TE];
    int t = threadIdx.x, w = t >> 5, l = t & 31;
    int base = blockIdx.x * TE;

    // Phase A: encode 4 edges per warp into A-fragment layout (affine offsets)
    for (int i = 0; i < 4; ++i) {
        int e = w * 4 + i, ge = base + e;
        if (ge < E) {
            float ss, s, e1, e2, e3;
            const float* nr = neigh + (size_t)ge * D_NODE;
            float v[4]; ss = 0.f;
#pragma unroll
            for (int m = 0; m < 4; ++m) { int o = l + 32 * m; v[m] = (o < 100) ? nr[o] : 0.f; ss += v[m] * v[m]; }
            ss = wsum32(ss); enc_scale(ss, s, e1);
            {
                int b0 = xs_base(e, l, 0);
#pragma unroll
                for (int m = 0; m < 4; ++m) if (l + 32 * m < 100) Xs[b0 + 512 * m] = tf32r(v[m] * s);
            }
            const float* er2 = edgef + (size_t)ge * D_EDGE;
            float u[6]; ss = 0.f;
#pragma unroll
            for (int m = 0; m < 6; ++m) { int o = l + 32 * m; u[m] = (o < 172) ? er2[o] : 0.f; ss += u[m] * u[m]; }
            ss = wsum32(ss); enc_scale(ss, s, e2);
            {
                int b1 = xs_base(e, l, 100);
#pragma unroll
                for (int m = 0; m < 6; ++m) if (l + 32 * m < 172) Xs[b1 + 512 * m] = tf32r(u[m] * s);
            }
            float dtv = dtp[ge];
            float cc[4]; ss = 0.f;
#pragma unroll
            for (int m = 0; m < 4; ++m) {
                int o = l + 32 * m;
                float c = (o < 100) ? __cosf(fmaf(dtv, tw[o], tb[o])) : 0.f;
                cc[m] = c; ss += c * c;
            }
            ss = wsum32(ss); enc_scale(ss, s, e3);
            {
                int b2 = xs_base(e, l, 272);
#pragma unroll
                for (int m = 0; m < 4; ++m) if (l + 32 * m < 100) Xs[b2 + 512 * m] = tf32r(cc[m] * s);
            }
            if (l < 12) xs_store(Xs, e, 372 + l, 0.f);
            if (l == 0) { s_xn[e] = fmaxf(sqrtf(e1 * e1 + e2 * e2 + e3 * e3), MINN); s_dst[e] = edst[ge]; }
        } else {
            for (int o = l; o < 384; o += 32) xs_store(Xs, e, o, 0.f);
            if (l == 0) { s_xn[e] = MINN; s_dst[e] = 0; }
        }
    }
    for (int o = t; o < 128; o += 512) {
        s_hbk[o] = (o < DOUT) ? g_hb[1 * DOUT + o] : 0.f;
        s_hbv[o] = (o < DOUT) ? g_hb[2 * DOUT + o] : 0.f;
    }
    if (t < TE) { s_pnk[t] = 0.f; s_pdk[t] = 0.f; s_pnv[t] = 0.f; s_pdv[t] = 0.f; }
    if (t == 0) { s_hb2k = g_hb2[1]; s_hb2v = g_hb2[2]; }
    __syncthreads();

    // GEMM: warp = (mat, mgroup of 2 mtiles, ngroup of 4 ntiles)
    int mat = w >> 3, mg = (w >> 2) & 1, ng = w & 3;
    float acc[2][4][4];
#pragma unroll
    for (int a = 0; a < 2; ++a)
#pragma unroll
        for (int b = 0; b < 4; ++b)
#pragma unroll
            for (int cxx = 0; cxx < 4; ++cxx) acc[a][b][cxx] = 0.f;

    const float2* Bg = (const float2*)(g_Bfrag) + ((mat * 16 + ng * 4) * 6) * 32 + l;
    for (int hc = 0; hc < 8; ++hc) {
        const float2* Bh = Bg + hc * 6144;
#pragma unroll
        for (int ksl = 0; ksl < 6; ++ksl) {
            int ks = hc * 6 + ksl;
            uint32_t a0[4], a1[4];
            *(float4*)a0 = *(const float4*)(Xs + (((2 * mg) * 48 + ks) * 32 + l) * 4);
            *(float4*)a1 = *(const float4*)(Xs + (((2 * mg + 1) * 48 + ks) * 32 + l) * 4);
            float2 bf[4];
#pragma unroll
            for (int nt4 = 0; nt4 < 4; ++nt4)
                bf[nt4] = __ldg(Bh + (nt4 * 6 + ksl) * 32);
#pragma unroll
            for (int nt4 = 0; nt4 < 4; ++nt4) {
                uint32_t b[2];
                *(float2*)b = bf[nt4];
                mma_tf32(acc[0][nt4], a0, b);
                mma_tf32(acc[1][nt4], a1, b);
            }
        }
    }

    // Register-level pn/pd partials (cols >= 100 have acc=0 and hb pad=0)
    const float* hbp = mat ? s_hbv : s_hbk;
    float* PN = mat ? s_pnv : s_pnk;
    float* PD = mat ? s_pdv : s_pdk;
#pragma unroll
    for (int mi = 0; mi < 2; ++mi) {
        float pn0 = 0.f, pd0 = 0.f, pn1 = 0.f, pd1 = 0.f;
#pragma unroll
        for (int nt4 = 0; nt4 < 4; ++nt4) {
            int nc = ng * 32 + nt4 * 8 + (l & 3) * 2;
            float h0 = hbp[nc], h1 = hbp[nc + 1];
            float a0 = acc[mi][nt4][0], a1 = acc[mi][nt4][1];
            float a2 = acc[mi][nt4][2], a3 = acc[mi][nt4][3];
            pn0 += a0 * a0 + a1 * a1; pd0 += a0 * h0 + a1 * h1;
            pn1 += a2 * a2 + a3 * a3; pd1 += a2 * h0 + a3 * h1;
        }
#pragma unroll
        for (int mk = 1; mk <= 2; mk <<= 1) {
            pn0 += __shfl_xor_sync(0xffffffffu, pn0, mk);
            pd0 += __shfl_xor_sync(0xffffffffu, pd0, mk);
            pn1 += __shfl_xor_sync(0xffffffffu, pn1, mk);
            pd1 += __shfl_xor_sync(0xffffffffu, pd1, mk);
        }
        if ((l & 3) == 0) {
            int rA = (2 * mg + mi) * 16 + (l >> 2);
            atomicAdd(&PN[rA], pn0); atomicAdd(&PD[rA], pd0);
            atomicAdd(&PN[rA + 8], pn1); atomicAdd(&PD[rA + 8], pd1);
        }
    }
    __syncthreads();

    // hyp_ab per (edge, mat) by first 128 threads
    if (t < 128) {
        int e = t & 63, m2 = t >> 6;
        float pn = m2 ? s_pnv[e] : s_pnk[e];
        float pd = m2 ? s_pdv[e] : s_pdk[e];
        float hb2 = m2 ? s_hb2v : s_hb2k;
        float al, be, np;
        hyp_ab(pn, s_xn[e], pd, hb2, al, be, np);
        s_al[m2][e] = al; s_be[m2][e] = be;
    }
    __syncthreads();

    // Stage scaled K/V into smem (overwrite Xs)
    float* Kt = Xs;               // [64][104]
    float* Vt = Xs + TE * 104;    // [64][104]
    {
        float* dst = mat ? Vt : Kt;
        const float* alr = s_al[mat];
        const float* ber = s_be[mat];
#pragma unroll
        for (int mi = 0; mi < 2; ++mi) {
            int rA = (2 * mg + mi) * 16 + (l >> 2);
            float alA = alr[rA], beA = ber[rA];
            float alB = alr[rA + 8], beB = ber[rA + 8];
#pragma unroll
            for (int nt4 = 0; nt4 < 4; ++nt4) {
                int nc = ng * 32 + nt4 * 8 + (l & 3) * 2;
                if (nc < 100) {
                    float h0 = hbp[nc], h1 = hbp[nc + 1];
                    dst[rA * 104 + nc]           = alA * acc[mi][nt4][0] + beA * h0;
                    dst[rA * 104 + nc + 1]       = alA * acc[mi][nt4][1] + beA * h1;
                    dst[(rA + 8) * 104 + nc]     = alB * acc[mi][nt4][2] + beB * h0;
                    dst[(rA + 8) * 104 + nc + 1] = alB * acc[mi][nt4][3] + beB * h1;
                }
            }
        }
    }
    __syncthreads();

    // Scores: 16 warps x 4 edges
    for (int i = 0; i < 4; ++i) {
        int e = w * 4 + i, ge = base + e;
        if (ge >= E) continue;
        int dv = s_dst[e];
        const float* q = g_Qd + (size_t)dv * DOUT;
        float s0 = 0.f, s1v = 0.f;
        for (int o = l; o < DOUT; o += 32) {
            float p = q[o] * Kt[e * 104 + o];
            if (o < 50) s0 += p; else s1v += p;
        }
        s0 = wsum32(s0); s1v = wsum32(s1v);
        if (l == 0) {
            float r0 = lrelu(s0), r1 = lrelu(s1v);
            g_scores[2 * ge] = r0; g_scores[2 * ge + 1] = r1;
            atomicMax(&g_smax[2 * dv], fenc(r0));
            atomicMax(&g_smax[2 * dv + 1], fenc(r1));
        }
    }
    // Coalesced V writeout
    for (int i = t; i < TE * 25; i += 512) {
        int e = i / 25, c4 = i % 25;
        int ge = base + e;
        if (ge < E) {
            float4 v = *(const float4*)(Vt + e * 104 + c4 * 4);
            *(float4*)(g_V + (size_t)ge * DOUT + c4 * 4) = v;
        }
    }
}

// ---------------- k3: exp + segment-sum + UNNORMALIZED scatter-aggregate -----
__global__ void k3_agg(const int* __restrict__ edst, int E) {
    int gw = (blockIdx.x * blockDim.x + threadIdx.x) >> 5;
    int l = threadIdx.x & 31;
    if (gw >= E) return;
    int d = edst[gw];
    float z0 = 0.f, z1 = 0.f;
    if (l == 0) {
        z0 = __expf(g_scores[2 * gw] - fdec(g_smax[2 * d]));
        z1 = __expf(g_scores[2 * gw + 1] - fdec(g_smax[2 * d + 1]));
        atomicAdd(&g_ssum[2 * d], z0);
        atomicAdd(&g_ssum[2 * d + 1], z1);
    }
    z0 = __shfl_sync(0xffffffffu, z0, 0);
    z1 = __shfl_sync(0xffffffffu, z1, 0);
    if (l < 25) {
        const float4* vr = (const float4*)(g_V + (size_t)gw * DOUT);
        float4 v = vr[l];
        int c0 = 4 * l;
        float4 r;
        r.x = v.x * (c0 + 0 < 50 ? z0 : z1);
        r.y = v.y * (c0 + 1 < 50 ? z0 : z1);
        r.z = v.z * (c0 + 2 < 50 ? z0 : z1);
        r.w = v.w * (c0 + 3 < 50 ? z0 : z1);
        float* hp = g_hagg + (size_t)d * DOUT + c0;
        asm volatile("red.global.add.v4.f32 [%0], {%1, %2, %3, %4};"
                     :: "l"(hp), "f"(r.x), "f"(r.y), "f"(r.z), "f"(r.w) : "memory");
    }
}

// ---------------- k5: normalize + O projection + HypAct + LayerNorm ----------
__global__ void __launch_bounds__(256) k5_final(const float* __restrict__ Wo,
                                                const float* __restrict__ lng,
                                                const float* __restrict__ lnb,
                                                float* __restrict__ out, int D) {
    extern __shared__ float sm[];
    float* Ws = sm;
    float* Xs = sm + 200 * WSP;
    __shared__ float s_xn[32];
    int t = threadIdx.x, w = t >> 5, l = t & 31;
    int rbase = blockIdx.x * 32;
    for (int i = 0; i < 4; ++i) {
        int r = w * 4 + i, gr = rbase + r;
        float* xr = Xs + r * 200;
        if (gr < D) {
            const float* ha = g_hagg + (size_t)gr * DOUT;
            const float* dh = g_dsthyp + (size_t)gr * D_NODE;
            float inv0 = 1.f / fmaxf(g_ssum[2 * gr], MINN);
            float inv1 = 1.f / fmaxf(g_ssum[2 * gr + 1], MINN);
            float ss = 0.f;
#pragma unroll
            for (int m = 0; m < 4; ++m) {
                int o = l + 32 * m;
                float a = (o < 100) ? ha[o] * (o < 50 ? inv0 : inv1) : 0.f;
                float b = (o < 100) ? dh[o] : 0.f;
                if (o < 100) { xr[o] = a; xr[100 + o] = b; }
                ss += a * a + b * b;
            }
            ss = wsum32(ss);
            if (l == 0) s_xn[r] = fmaxf(sqrtf(ss), MINN);
        } else {
            for (int o = l; o < 200; o += 32) xr[o] = 0.f;
            if (l == 0) s_xn[r] = MINN;
        }
    }
    for (int i = t; i < 5 * 200; i += 256) { int o = 100 + i / 200, k = i % 200; Ws[k * WSP + o] = 0.f; }
    for (int i = t; i < 100 * 200; i += 256) { int o = i / 200, k = i % 200; Ws[k * WSP + o] = Wo[i]; }
    __syncthreads();
    int oc = t & 127, g = t >> 7;
    int ocw = (oc < WSP) ? oc : 0;
    float acc[16];
#pragma unroll
    for (int rr = 0; rr < 16; ++rr) acc[rr] = 0.f;
    for (int k = 0; k < 200; ++k) {
        float wv = Ws[k * WSP + ocw];
#pragma unroll
        for (int rr = 0; rr < 16; ++rr) acc[rr] = fmaf(Xs[(g * 16 + rr) * 200 + k], wv, acc[rr]);
    }
    __syncthreads();
    float* Ms = Ws;
    if (oc < 100) {
#pragma unroll
        for (int rr = 0; rr < 16; ++rr) Ms[(g * 16 + rr) * 104 + oc] = acc[rr];
    }
    __syncthreads();
    float hb2 = g_hb2[3];
    for (int i = 0; i < 4; ++i) {
        int r = w * 4 + i, gr = rbase + r;
        if (gr >= D) continue;
        float mv[4], hv[4]; float pn = 0.f, pd = 0.f;
#pragma unroll
        for (int m = 0; m < 4; ++m) {
            int o = l + 32 * m;
            float a = (o < 100) ? Ms[r * 104 + o] : 0.f;
            float h = (o < 100) ? g_hb[3 * DOUT + o] : 0.f;
            mv[m] = a; hv[m] = h; pn += a * a; pd += a * h;
        }
        pn = wsum32(pn); pd = wsum32(pd);
        float alpha, beta, nprev;
        hyp_ab(pn, s_xn[r], pd, hb2, alpha, beta, nprev);
        float lc = artanh_f(nprev) / fmaxf(nprev, MINN);
        float u2v[4]; float uss = 0.f;
#pragma unroll
        for (int m = 0; m < 4; ++m) {
            float u2 = lrelu(lc * (alpha * mv[m] + beta * hv[m]));
            u2v[m] = u2; uss += u2 * u2;
        }
        uss = wsum32(uss);
        float s2, en3; enc_scale(uss, s2, en3);
        float hsc = artanh_f(en3) / fmaxf(en3, MINN) * s2;
        float hvv[4]; float hs = 0.f, hs2 = 0.f;
#pragma unroll
        for (int m = 0; m < 4; ++m) {
            int o = l + 32 * m;
            float h = hsc * u2v[m];
            hvv[m] = h;
            if (o < 100) { hs += h; hs2 += h * h; }
        }
        hs = wsum32(hs); hs2 = wsum32(hs2);
        float mu = hs * 0.01f;
        float var = hs2 * 0.01f - mu * mu;
        float inv = rsqrtf(var + 1e-5f);
#pragma unroll
        for (int m = 0; m < 4; ++m) {
            int o = l + 32 * m;
            if (o < 100) out[(size_t)gr * 100 + o] = (hvv[m] - mu) * inv * lng[o] + lnb[o];
        }
    }
}

extern "C" void kernel_launch(void* const* d_in, const int* in_sizes, int n_in,
                              void* d_out, int out_size) {
    const float* dst_h = (const float*)d_in[0];
    const float* neigh = (const float*)d_in[1];
    const float* edgef = (const float*)d_in[2];
    const float* dtp   = (const float*)d_in[3];
    const int*   edst  = (const int*)d_in[4];
    const float* Wq = (const float*)d_in[5];
    const float* bq = (const float*)d_in[6];
    const float* Wk = (const float*)d_in[7];
    const float* bk = (const float*)d_in[8];
    const float* Wv = (const float*)d_in[9];
    const float* bv = (const float*)d_in[10];
    const float* Wo = (const float*)d_in[11];
    const float* bo = (const float*)d_in[12];
    const float* tw = (const float*)d_in[13];
    const float* tb = (const float*)d_in[14];
    const float* lng = (const float*)d_in[15];
    const float* lnb = (const float*)d_in[16];
    float* out = (float*)d_out;
    int D = in_sizes[0] / D_NODE;
    int E = in_sizes[3];

    void *p_hagg = nullptr, *p_ssum = nullptr, *p_smax = nullptr;
    cudaGetSymbolAddress(&p_hagg, g_hagg);
    cudaGetSymbolAddress(&p_ssum, g_ssum);
    cudaGetSymbolAddress(&p_smax, g_smax);
    cudaMemsetAsync(p_hagg, 0, (size_t)D * DOUT * sizeof(float));
    cudaMemsetAsync(p_ssum, 0, (size_t)2 * D * sizeof(float));
    cudaMemsetAsync(p_smax, 0, (size_t)2 * D * sizeof(unsigned));

    size_t smem1 = (200 * WSP + 32 * 200) * sizeof(float);   // 109600
    size_t smem2 = 24576 * sizeof(float);                    // 98304 -> 2 CTAs/SM
    cudaFuncSetAttribute(k1_dst,   cudaFuncAttributeMaxDynamicSharedMemorySize, (int)smem1);
    cudaFuncSetAttribute(k5_final, cudaFuncAttributeMaxDynamicSharedMemorySize, (int)smem1);
    cudaFuncSetAttribute(k2_edge,  cudaFuncAttributeMaxDynamicSharedMemorySize, (int)smem2);

    k_small<<<1, 160>>>(bq, bk, bv, bo, tb);
    k_bfrag<<<(8 * 12288 + 255) / 256, 256>>>(Wk, Wv);
    k1_dst<<<(D + 31) / 32, 256, smem1>>>(dst_h, Wq, D);
    k2_edge<<<(E + TE - 1) / TE, 512, smem2>>>(neigh, edgef, dtp, edst, tw, tb, E);
    k3_agg<<<(E + 7) / 8, 256>>>(edst, E);
    k5_final<<<(D + 31) / 32, 256, smem1>>>(Wo, lng, lnb, out, D);
}